// round 3
// baseline (speedup 1.0000x reference)
#include <cuda_runtime.h>
#include <math.h>

// Problem constants
#define NB   4
#define NLQ  512
#define NLKV 2048
#define NDIM 1024
#define NH   16
#define NHD  64
#define NMH  4096

#define MQ (NB * NLQ)    // 2048 query rows
#define MKV (NB * NLKV)  // 8192 kv rows

// ---------------------------------------------------------------------------
// Scratch (device globals; no allocation allowed)
// ---------------------------------------------------------------------------
__device__ float g_qn [MQ  * NDIM];
__device__ float g_kvn[MKV * NDIM];
__device__ float g_q  [MQ  * NDIM];
__device__ float g_k  [MKV * NDIM];
__device__ float g_v  [MKV * NDIM];
__device__ float g_ctx[MQ  * NDIM];
__device__ float g_res[MQ  * NDIM];
__device__ float g_hn [MQ  * NDIM];
__device__ float g_h1 [MQ  * NMH];

// ---------------------------------------------------------------------------
// LayerNorm: one block per row of 1024, 256 threads, float4 per thread
// ---------------------------------------------------------------------------
__global__ __launch_bounds__(256) void ln_kernel(
    const float* __restrict__ x, const float* __restrict__ w,
    const float* __restrict__ bp, float* __restrict__ y)
{
    const int row = blockIdx.x;
    const int tid = threadIdx.x;
    const float4 xv = *(const float4*)(x + (size_t)row * NDIM + tid * 4);
    float s  = xv.x + xv.y + xv.z + xv.w;
    float ss = fmaf(xv.x, xv.x, fmaf(xv.y, xv.y, fmaf(xv.z, xv.z, xv.w * xv.w)));

    __shared__ float rs[8], rss[8];
#pragma unroll
    for (int o = 16; o > 0; o >>= 1) {
        s  += __shfl_xor_sync(0xffffffffu, s,  o);
        ss += __shfl_xor_sync(0xffffffffu, ss, o);
    }
    if ((tid & 31) == 0) { rs[tid >> 5] = s; rss[tid >> 5] = ss; }
    __syncthreads();
    float st = 0.f, sst = 0.f;
#pragma unroll
    for (int i = 0; i < 8; i++) { st += rs[i]; sst += rss[i]; }

    const float mu  = st * (1.f / NDIM);
    const float var = sst * (1.f / NDIM) - mu * mu;
    const float inv = rsqrtf(var + 1e-6f);

    const float4 wv = *(const float4*)(w + tid * 4);
    const float4 bv = *(const float4*)(bp + tid * 4);
    float4 o;
    o.x = (xv.x - mu) * inv * wv.x + bv.x;
    o.y = (xv.y - mu) * inv * wv.y + bv.y;
    o.z = (xv.z - mu) * inv * wv.z + bv.z;
    o.w = (xv.w - mu) * inv * wv.w + bv.w;
    *(float4*)(y + (size_t)row * NDIM + tid * 4) = o;
}

// ---------------------------------------------------------------------------
// Per-head L2 normalize: rows of 64 contiguous floats. One warp per row,
// 8 rows per 256-thread block. grid = nrows/8 (exact).
// ---------------------------------------------------------------------------
__global__ __launch_bounds__(256) void l2norm_kernel(float* __restrict__ x)
{
    const int row  = blockIdx.x * 8 + (threadIdx.x >> 5);
    const int lane = threadIdx.x & 31;
    float2* p = (float2*)(x + (size_t)row * 64) + lane;
    float2 v = *p;
    float ss = v.x * v.x + v.y * v.y;
#pragma unroll
    for (int o = 16; o > 0; o >>= 1) ss += __shfl_xor_sync(0xffffffffu, ss, o);
    const float inv = 1.f / fmaxf(sqrtf(ss), 1e-6f);
    v.x *= inv; v.y *= inv;
    *p = v;
}

// ---------------------------------------------------------------------------
// GEMM: C[M,N] = A[M,K] @ W[N,K]^T (both K-contiguous). 128x128x16 tiles,
// 256 threads, 8x8 microtile. Dims are multiples of 128/16 -> no bounds checks.
// EPI: 0 = plain, 1 = res + alpha*(acc + bias), 2 = gelu(acc + bias)
// ---------------------------------------------------------------------------
__device__ __forceinline__ float gelu_f(float x) {
    return 0.5f * x * (1.0f + erff(x * 0.70710678118654752440f));
}

template<int EPI>
__global__ __launch_bounds__(256) void gemm_kernel(
    const float* __restrict__ A, const float* __restrict__ W,
    const float* __restrict__ bias, const float* __restrict__ res,
    const float* __restrict__ alpha_p, float* __restrict__ C,
    int M, int N, int K)
{
    __shared__ float As[16][132];
    __shared__ float Bs[16][132];
    const int tid = threadIdx.x;
    const int tx = tid & 15;
    const int ty = tid >> 4;
    const int ar = tid >> 2;
    const int ac = (tid & 3) << 2;
    const float* Ab = A + (size_t)blockIdx.y * 128 * K;
    const float* Wb = W + (size_t)blockIdx.x * 128 * K;

    float acc[8][8];
#pragma unroll
    for (int i = 0; i < 8; i++)
#pragma unroll
        for (int j = 0; j < 8; j++) acc[i][j] = 0.f;

    for (int k0 = 0; k0 < K; k0 += 16) {
        const float4 a0 = *(const float4*)(Ab + (size_t)ar        * K + k0 + ac);
        const float4 a1 = *(const float4*)(Ab + (size_t)(ar + 64) * K + k0 + ac);
        const float4 b0 = *(const float4*)(Wb + (size_t)ar        * K + k0 + ac);
        const float4 b1 = *(const float4*)(Wb + (size_t)(ar + 64) * K + k0 + ac);
        __syncthreads();
        As[ac+0][ar] = a0.x; As[ac+1][ar] = a0.y; As[ac+2][ar] = a0.z; As[ac+3][ar] = a0.w;
        As[ac+0][ar+64] = a1.x; As[ac+1][ar+64] = a1.y; As[ac+2][ar+64] = a1.z; As[ac+3][ar+64] = a1.w;
        Bs[ac+0][ar] = b0.x; Bs[ac+1][ar] = b0.y; Bs[ac+2][ar] = b0.z; Bs[ac+3][ar] = b0.w;
        Bs[ac+0][ar+64] = b1.x; Bs[ac+1][ar+64] = b1.y; Bs[ac+2][ar+64] = b1.z; Bs[ac+3][ar+64] = b1.w;
        __syncthreads();
#pragma unroll
        for (int kk = 0; kk < 16; kk++) {
            const float4 xa0 = *(const float4*)&As[kk][ty * 4];
            const float4 xa1 = *(const float4*)&As[kk][ty * 4 + 64];
            const float4 xb0 = *(const float4*)&Bs[kk][tx * 4];
            const float4 xb1 = *(const float4*)&Bs[kk][tx * 4 + 64];
            const float ra[8] = {xa0.x, xa0.y, xa0.z, xa0.w, xa1.x, xa1.y, xa1.z, xa1.w};
            const float rb[8] = {xb0.x, xb0.y, xb0.z, xb0.w, xb1.x, xb1.y, xb1.z, xb1.w};
#pragma unroll
            for (int i = 0; i < 8; i++)
#pragma unroll
                for (int j = 0; j < 8; j++)
                    acc[i][j] = fmaf(ra[i], rb[j], acc[i][j]);
        }
    }

    float alpha = 0.f;
    if (EPI == 1) alpha = *alpha_p;

#pragma unroll
    for (int ig = 0; ig < 2; ig++) {
#pragma unroll
        for (int i = 0; i < 4; i++) {
            const int gm = blockIdx.y * 128 + ig * 64 + ty * 4 + i;
            float* crow = C + (size_t)gm * N + blockIdx.x * 128;
#pragma unroll
            for (int jg = 0; jg < 2; jg++) {
                const int cn = jg * 64 + tx * 4;
                float4 v = make_float4(acc[ig*4+i][jg*4+0], acc[ig*4+i][jg*4+1],
                                       acc[ig*4+i][jg*4+2], acc[ig*4+i][jg*4+3]);
                if (EPI == 1) {
                    const float4 bb = *(const float4*)&bias[blockIdx.x * 128 + cn];
                    const float4 rr = *(const float4*)(res + (size_t)gm * N + blockIdx.x * 128 + cn);
                    v.x = rr.x + alpha * (v.x + bb.x);
                    v.y = rr.y + alpha * (v.y + bb.y);
                    v.z = rr.z + alpha * (v.z + bb.z);
                    v.w = rr.w + alpha * (v.w + bb.w);
                } else if (EPI == 2) {
                    const float4 bb = *(const float4*)&bias[blockIdx.x * 128 + cn];
                    v.x = gelu_f(v.x + bb.x);
                    v.y = gelu_f(v.y + bb.y);
                    v.z = gelu_f(v.z + bb.z);
                    v.w = gelu_f(v.w + bb.w);
                }
                *(float4*)&crow[cn] = v;
            }
        }
    }
}

// ---------------------------------------------------------------------------
// Flash attention, fp32. Block = one (b, h, 64-row q tile). 256 threads.
// Online softmax over 32 kv tiles of 64. Scores * (1/TAU), TAU = 2.
// SMEM (dynamic, 70400 B): Qs[q][d], Kst[d][kv], Vs[kv][d], Ss[q][kv], pad 68.
// ---------------------------------------------------------------------------
#define ATTN_SMEM_BYTES ((4 * 64 * 68 + 3 * 64) * 4)

__global__ __launch_bounds__(256) void attn_kernel(
    const float* __restrict__ Q, const float* __restrict__ K,
    const float* __restrict__ V, float* __restrict__ O)
{
    extern __shared__ float sm[];
    float* Qs    = sm;
    float* Kst   = sm + 64 * 68;
    float* Vs    = sm + 2 * 64 * 68;
    float* Ss    = sm + 3 * 64 * 68;
    float* row_m = sm + 4 * 64 * 68;
    float* row_l = row_m + 64;
    float* row_c = row_l + 64;

    const int tid = threadIdx.x;
    const int tx = tid & 15;
    const int ty = tid >> 4;
    const int qt = blockIdx.x, h = blockIdx.y, b = blockIdx.z;

    const float* Qb = Q + ((size_t)(b * NLQ + qt * 64)) * NDIM + h * NHD;
    const float* Kb = K + ((size_t)b * NLKV) * NDIM + h * NHD;
    const float* Vb = V + ((size_t)b * NLKV) * NDIM + h * NHD;

#pragma unroll
    for (int it = 0; it < 4; it++) {
        const int idx = tid + it * 256;
        const int r = idx >> 4, c4 = idx & 15;
        *(float4*)&Qs[r * 68 + c4 * 4] = *(const float4*)&Qb[(size_t)r * NDIM + c4 * 4];
    }
    if (tid < 64) { row_m[tid] = -1e30f; row_l[tid] = 0.f; }

    float oacc[4][4];
#pragma unroll
    for (int i = 0; i < 4; i++)
#pragma unroll
        for (int j = 0; j < 4; j++) oacc[i][j] = 0.f;

    for (int kt = 0; kt < NLKV / 64; kt++) {
        __syncthreads();  // protect Kst/Vs/Ss from previous iteration's readers
#pragma unroll
        for (int it = 0; it < 4; it++) {
            const int idx = tid + it * 256;
            const int r = idx >> 4, c4 = idx & 15;
            const size_t grow = (size_t)(kt * 64 + r) * NDIM + c4 * 4;
            const float4 kk4 = *(const float4*)&Kb[grow];
            Kst[(c4 * 4 + 0) * 68 + r] = kk4.x;
            Kst[(c4 * 4 + 1) * 68 + r] = kk4.y;
            Kst[(c4 * 4 + 2) * 68 + r] = kk4.z;
            Kst[(c4 * 4 + 3) * 68 + r] = kk4.w;
            *(float4*)&Vs[r * 68 + c4 * 4] = *(const float4*)&Vb[grow];
        }
        __syncthreads();

        // S = Q K^T  (4x4 per thread)
        float s[4][4];
#pragma unroll
        for (int i = 0; i < 4; i++)
#pragma unroll
            for (int j = 0; j < 4; j++) s[i][j] = 0.f;
#pragma unroll
        for (int d4 = 0; d4 < 16; d4++) {
            float qr[4][4], kc[4][4];
#pragma unroll
            for (int u = 0; u < 4; u++) {
                const float4 t  = *(const float4*)&Qs [(ty * 4 + u) * 68 + d4 * 4];
                qr[u][0] = t.x; qr[u][1] = t.y; qr[u][2] = t.z; qr[u][3] = t.w;
                const float4 kk = *(const float4*)&Kst[(d4 * 4 + u) * 68 + tx * 4];
                kc[u][0] = kk.x; kc[u][1] = kk.y; kc[u][2] = kk.z; kc[u][3] = kk.w;
            }
#pragma unroll
            for (int i = 0; i < 4; i++)
#pragma unroll
                for (int dd = 0; dd < 4; dd++)
#pragma unroll
                    for (int j = 0; j < 4; j++)
                        s[i][j] = fmaf(qr[i][dd], kc[dd][j], s[i][j]);
        }
#pragma unroll
        for (int i = 0; i < 4; i++)
            *(float4*)&Ss[(ty * 4 + i) * 68 + tx * 4] =
                make_float4(s[i][0] * 0.5f, s[i][1] * 0.5f, s[i][2] * 0.5f, s[i][3] * 0.5f);
        __syncthreads();

        // Online softmax: one thread per q-row (2 warps active)
        if (tid < 64) {
            float* sr = &Ss[tid * 68];
            const float mo = row_m[tid];
            float mt = mo;
            for (int j = 0; j < 64; j++) mt = fmaxf(mt, sr[j]);
            const float c = __expf(mo - mt);
            float l = row_l[tid] * c;
            for (int j = 0; j < 64; j++) { const float p = __expf(sr[j] - mt); sr[j] = p; l += p; }
            row_m[tid] = mt; row_l[tid] = l; row_c[tid] = c;
        }
        __syncthreads();

        {
            const float c0 = row_c[ty * 4 + 0], c1 = row_c[ty * 4 + 1];
            const float c2 = row_c[ty * 4 + 2], c3 = row_c[ty * 4 + 3];
#pragma unroll
            for (int j = 0; j < 4; j++) {
                oacc[0][j] *= c0; oacc[1][j] *= c1; oacc[2][j] *= c2; oacc[3][j] *= c3;
            }
        }

        // O += P V
#pragma unroll
        for (int k4 = 0; k4 < 16; k4++) {
            float pr[4][4], vc[4][4];
#pragma unroll
            for (int u = 0; u < 4; u++) {
                const float4 t  = *(const float4*)&Ss[(ty * 4 + u) * 68 + k4 * 4];
                pr[u][0] = t.x; pr[u][1] = t.y; pr[u][2] = t.z; pr[u][3] = t.w;
                const float4 vv = *(const float4*)&Vs[(k4 * 4 + u) * 68 + tx * 4];
                vc[u][0] = vv.x; vc[u][1] = vv.y; vc[u][2] = vv.z; vc[u][3] = vv.w;
            }
#pragma unroll
            for (int i = 0; i < 4; i++)
#pragma unroll
                for (int kk = 0; kk < 4; kk++)
#pragma unroll
                    for (int j = 0; j < 4; j++)
                        oacc[i][j] = fmaf(pr[i][kk], vc[kk][j], oacc[i][j]);
        }
    }

    float* Ob = O + ((size_t)(b * NLQ + qt * 64)) * NDIM + h * NHD;
#pragma unroll
    for (int i = 0; i < 4; i++) {
        const float inv = 1.f / row_l[ty * 4 + i];
        const float4 o = make_float4(oacc[i][0] * inv, oacc[i][1] * inv,
                                     oacc[i][2] * inv, oacc[i][3] * inv);
        *(float4*)&Ob[(size_t)(ty * 4 + i) * NDIM + tx * 4] = o;
    }
}

// ---------------------------------------------------------------------------
// Launch
// ---------------------------------------------------------------------------
extern "C" void kernel_launch(void* const* d_in, const int* in_sizes, int n_in,
                              void* d_out, int out_size)
{
    (void)in_sizes; (void)n_in; (void)out_size;
    const float* q_tokens   = (const float*)d_in[0];
    const float* kv_tokens  = (const float*)d_in[1];
    const float* q_ln_w     = (const float*)d_in[2];
    const float* q_ln_b     = (const float*)d_in[3];
    const float* kv_ln_w    = (const float*)d_in[4];
    const float* kv_ln_b    = (const float*)d_in[5];
    const float* mlp_ln_w   = (const float*)d_in[6];
    const float* mlp_ln_b   = (const float*)d_in[7];
    const float* Wq         = (const float*)d_in[8];
    const float* Wk         = (const float*)d_in[9];
    const float* Wv         = (const float*)d_in[10];
    const float* Wo         = (const float*)d_in[11];
    const float* bo         = (const float*)d_in[12];
    const float* fc1_w      = (const float*)d_in[13];
    const float* fc1_b      = (const float*)d_in[14];
    const float* fc2_w      = (const float*)d_in[15];
    const float* fc2_b      = (const float*)d_in[16];
    const float* alpha_attn = (const float*)d_in[17];
    const float* alpha_mlp  = (const float*)d_in[18];
    float* out = (float*)d_out;

    void* p;
    float *QN, *KVN, *Qm, *Km, *Vm, *CTX, *RES, *HN, *H1;
    cudaGetSymbolAddress(&p, g_qn);  QN  = (float*)p;
    cudaGetSymbolAddress(&p, g_kvn); KVN = (float*)p;
    cudaGetSymbolAddress(&p, g_q);   Qm  = (float*)p;
    cudaGetSymbolAddress(&p, g_k);   Km  = (float*)p;
    cudaGetSymbolAddress(&p, g_v);   Vm  = (float*)p;
    cudaGetSymbolAddress(&p, g_ctx); CTX = (float*)p;
    cudaGetSymbolAddress(&p, g_res); RES = (float*)p;
    cudaGetSymbolAddress(&p, g_hn);  HN  = (float*)p;
    cudaGetSymbolAddress(&p, g_h1);  H1  = (float*)p;

    // 1) LayerNorms of inputs
    ln_kernel<<<MQ, 256>>>(q_tokens, q_ln_w, q_ln_b, QN);
    ln_kernel<<<MKV, 256>>>(kv_tokens, kv_ln_w, kv_ln_b, KVN);

    // 2) Q/K/V projections
    gemm_kernel<0><<<dim3(NDIM/128, MQ/128),  256>>>(QN,  Wq, nullptr, nullptr, nullptr, Qm, MQ,  NDIM, NDIM);
    gemm_kernel<0><<<dim3(NDIM/128, MKV/128), 256>>>(KVN, Wk, nullptr, nullptr, nullptr, Km, MKV, NDIM, NDIM);
    gemm_kernel<0><<<dim3(NDIM/128, MKV/128), 256>>>(KVN, Wv, nullptr, nullptr, nullptr, Vm, MKV, NDIM, NDIM);

    // 3) Per-head L2 normalization of q and k
    l2norm_kernel<<<(MQ  * NH) / 8, 256>>>(Qm);
    l2norm_kernel<<<(MKV * NH) / 8, 256>>>(Km);

    // 4) Attention
    cudaFuncSetAttribute(attn_kernel, cudaFuncAttributeMaxDynamicSharedMemorySize, ATTN_SMEM_BYTES);
    attn_kernel<<<dim3(NLQ/64, NH, NB), 256, ATTN_SMEM_BYTES>>>(Qm, Km, Vm, CTX);

    // 5) Output projection + attn residual: RES = q_tokens + alpha_attn*(CTX@Wo^T + bo)
    gemm_kernel<1><<<dim3(NDIM/128, MQ/128), 256>>>(CTX, Wo, bo, q_tokens, alpha_attn, RES, MQ, NDIM, NDIM);

    // 6) MLP
    ln_kernel<<<MQ, 256>>>(RES, mlp_ln_w, mlp_ln_b, HN);
    gemm_kernel<2><<<dim3(NMH/128, MQ/128), 256>>>(HN, fc1_w, fc1_b, nullptr, nullptr, H1, MQ, NMH, NDIM);
    gemm_kernel<1><<<dim3(NDIM/128, MQ/128), 256>>>(H1, fc2_w, fc2_b, RES, alpha_mlp, out, MQ, NDIM, NMH);
}

// round 5
// speedup vs baseline: 2.5474x; 2.5474x over previous
#include <cuda_runtime.h>
#include <cuda_bf16.h>
#include <math.h>
#include <stdint.h>

// Problem constants
#define NB   4
#define NLQ  512
#define NLKV 2048
#define NDIM 1024
#define NH   16
#define NHD  64
#define NMH  4096

#define MQ  (NB * NLQ)    // 2048
#define MKV (NB * NLKV)   // 8192

// ---------------------------------------------------------------------------
// Scratch (device globals; no allocation allowed)
// ---------------------------------------------------------------------------
__device__ __align__(256) __nv_bfloat16 g_qnb [MQ  * NDIM];
__device__ __align__(256) __nv_bfloat16 g_kvnb[MKV * NDIM];
__device__ __align__(256) __nv_bfloat16 g_ctxb[MQ  * NDIM];
__device__ __align__(256) __nv_bfloat16 g_hnb [MQ  * NDIM];
__device__ __align__(256) __nv_bfloat16 g_h1b [MQ  * NMH];
__device__ __align__(256) __nv_bfloat16 g_wqb [NDIM * NDIM];
__device__ __align__(256) __nv_bfloat16 g_wkb [NDIM * NDIM];
__device__ __align__(256) __nv_bfloat16 g_wvb [NDIM * NDIM];
__device__ __align__(256) __nv_bfloat16 g_wob [NDIM * NDIM];
__device__ __align__(256) __nv_bfloat16 g_f1b [NMH * NDIM];
__device__ __align__(256) __nv_bfloat16 g_f2b [NDIM * NMH];

__device__ __align__(256) float g_q  [MQ  * NDIM];
__device__ __align__(256) float g_k  [MKV * NDIM];
__device__ __align__(256) float g_v  [MKV * NDIM];
__device__ __align__(256) float g_res[MQ  * NDIM];

// ---------------------------------------------------------------------------
// PTX helpers (sm_80-era: cp.async, ldmatrix, mma.sync — legal on sm_103)
// ---------------------------------------------------------------------------
__device__ __forceinline__ uint32_t smem_u32(const void* p) {
    uint32_t a;
    asm("{ .reg .u64 t; cvta.to.shared.u64 t, %1; cvt.u32.u64 %0, t; }"
        : "=r"(a) : "l"(p));
    return a;
}

__device__ __forceinline__ void cp16(uint32_t dst, const void* src) {
    asm volatile("cp.async.cg.shared.global [%0], [%1], 16;" :: "r"(dst), "l"(src));
}
#define CP_COMMIT() asm volatile("cp.async.commit_group;" ::: "memory")
#define CP_WAIT1()  asm volatile("cp.async.wait_group 1;"  ::: "memory")

__device__ __forceinline__ void ldm_x4(uint32_t* r, uint32_t addr) {
    asm volatile("ldmatrix.sync.aligned.m8n8.x4.shared.b16 {%0,%1,%2,%3}, [%4];"
        : "=r"(r[0]), "=r"(r[1]), "=r"(r[2]), "=r"(r[3]) : "r"(addr));
}

__device__ __forceinline__ void mma16816(float* c, const uint32_t* a,
                                         uint32_t b0, uint32_t b1) {
    asm volatile(
        "mma.sync.aligned.m16n8k16.row.col.f32.bf16.bf16.f32 "
        "{%0,%1,%2,%3}, {%4,%5,%6,%7}, {%8,%9}, {%0,%1,%2,%3};"
        : "+f"(c[0]), "+f"(c[1]), "+f"(c[2]), "+f"(c[3])
        : "r"(a[0]), "r"(a[1]), "r"(a[2]), "r"(a[3]), "r"(b0), "r"(b1));
}

__device__ __forceinline__ uint32_t pk2(float a, float b) {
    return ((uint32_t)__bfloat16_as_ushort(__float2bfloat16(b)) << 16)
         |  (uint32_t)__bfloat16_as_ushort(__float2bfloat16(a));
}

__device__ __forceinline__ float gelu_f(float x) {
    return 0.5f * x * (1.0f + erff(x * 0.70710678118654752440f));
}

// ---------------------------------------------------------------------------
// fp32 -> bf16 conversion (4 elems/thread)
// ---------------------------------------------------------------------------
__global__ __launch_bounds__(256) void conv_kernel(
    const float* __restrict__ s, __nv_bfloat16* __restrict__ d)
{
    const int i = (blockIdx.x * 256 + threadIdx.x) * 4;
    const float4 v = *(const float4*)(s + i);
    *(uint2*)(d + i) = make_uint2(pk2(v.x, v.y), pk2(v.z, v.w));
}

// ---------------------------------------------------------------------------
// LayerNorm -> bf16 output. One block per row of 1024.
// ---------------------------------------------------------------------------
__global__ __launch_bounds__(256) void ln_bf16_kernel(
    const float* __restrict__ x, const float* __restrict__ w,
    const float* __restrict__ bp, __nv_bfloat16* __restrict__ y)
{
    const int row = blockIdx.x;
    const int tid = threadIdx.x;
    const float4 xv = *(const float4*)(x + (size_t)row * NDIM + tid * 4);
    float s  = xv.x + xv.y + xv.z + xv.w;
    float ss = fmaf(xv.x, xv.x, fmaf(xv.y, xv.y, fmaf(xv.z, xv.z, xv.w * xv.w)));

    __shared__ float rs[8], rss[8];
#pragma unroll
    for (int o = 16; o > 0; o >>= 1) {
        s  += __shfl_xor_sync(0xffffffffu, s,  o);
        ss += __shfl_xor_sync(0xffffffffu, ss, o);
    }
    if ((tid & 31) == 0) { rs[tid >> 5] = s; rss[tid >> 5] = ss; }
    __syncthreads();
    float st = 0.f, sst = 0.f;
#pragma unroll
    for (int i = 0; i < 8; i++) { st += rs[i]; sst += rss[i]; }

    const float mu  = st * (1.f / NDIM);
    const float var = sst * (1.f / NDIM) - mu * mu;
    const float inv = rsqrtf(var + 1e-6f);

    const float4 wv = *(const float4*)(w + tid * 4);
    const float4 bv = *(const float4*)(bp + tid * 4);
    float4 o;
    o.x = (xv.x - mu) * inv * wv.x + bv.x;
    o.y = (xv.y - mu) * inv * wv.y + bv.y;
    o.z = (xv.z - mu) * inv * wv.z + bv.z;
    o.w = (xv.w - mu) * inv * wv.w + bv.w;
    *(uint2*)(y + (size_t)row * NDIM + tid * 4) = make_uint2(pk2(o.x, o.y), pk2(o.z, o.w));
}

// ---------------------------------------------------------------------------
// Per-head L2 normalize (fp32 in-place), rows of 64 floats, 1 warp per row
// ---------------------------------------------------------------------------
__global__ __launch_bounds__(256) void l2norm_kernel(float* __restrict__ x)
{
    const int row  = blockIdx.x * 8 + (threadIdx.x >> 5);
    const int lane = threadIdx.x & 31;
    float2* p = (float2*)(x + (size_t)row * 64) + lane;
    float2 v = *p;
    float ss = v.x * v.x + v.y * v.y;
#pragma unroll
    for (int o = 16; o > 0; o >>= 1) ss += __shfl_xor_sync(0xffffffffu, ss, o);
    const float inv = 1.f / fmaxf(sqrtf(ss), 1e-6f);
    v.x *= inv; v.y *= inv;
    *p = v;
}

// ---------------------------------------------------------------------------
// mma.sync bf16 GEMM:  C[M,N] = A[M,K] @ B[N,K]^T   (A, B bf16, K-contiguous)
// BM=128, BN=128, BK=64, 3-stage cp.async pipeline, 256 threads (8 warps,
// 2x4 layout, 64x32 warp tiles), fp32 accumulators.
// SMEM: per stage A 128x128B + B 128x128B (XOR-swizzled for ldmatrix).
// EPI: 0 = fp32 out; 1 = fp32 out = res + alpha*(acc+bias); 2 = bf16 gelu(acc+bias)
// ---------------------------------------------------------------------------
#define STG_BYTES (128 * 128 * 2)     // 32768 (A 16KB + B 16KB)
#define GEMM_SMEM (3 * STG_BYTES)     // 98304

template<int EPI>
__global__ __launch_bounds__(256) void gemm_mma(
    const __nv_bfloat16* __restrict__ A, const __nv_bfloat16* __restrict__ B,
    const float* __restrict__ bias, const float* __restrict__ res,
    const float* __restrict__ alpha_p,
    float* __restrict__ Cf, __nv_bfloat16* __restrict__ Cb,
    int M, int N, int K)
{
    extern __shared__ char dyn[];
    const uint32_t base = smem_u32(dyn);
    const int tid  = threadIdx.x;
    const int wid  = tid >> 5, lane = tid & 31;
    const int mw   = wid & 1;         // 0..1  (m dimension)
    const int nw   = wid >> 1;        // 0..3  (n dimension)

    const __nv_bfloat16* Ab = A + (size_t)blockIdx.y * 128 * K;
    const __nv_bfloat16* Bb = B + (size_t)blockIdx.x * 128 * K;
    const int NK = K / 64;

    // Loader: each thread copies 4 A-chunks + 4 B-chunks of 16B.
    const int lrow = tid >> 1;            // 0..127
    const int lc0  = (tid & 1) * 4;       // 0 or 4
    const int lsw  = lrow & 7;

    float acc[4][4][4];
#pragma unroll
    for (int mi = 0; mi < 4; mi++)
#pragma unroll
        for (int ni = 0; ni < 4; ni++)
#pragma unroll
            for (int e = 0; e < 4; e++) acc[mi][ni][e] = 0.f;

    // prefill stages 0,1
#pragma unroll
    for (int p = 0; p < 2; p++) {
        const uint32_t sA = base + p * STG_BYTES;
        const uint32_t sB = sA + 128 * 128;
        const __nv_bfloat16* ag = Ab + (size_t)lrow * K + p * 64 + lc0 * 8;
        const __nv_bfloat16* bg = Bb + (size_t)lrow * K + p * 64 + lc0 * 8;
#pragma unroll
        for (int i = 0; i < 4; i++) {
            const int c = lc0 + i;
            cp16(sA + lrow * 128 + ((c ^ lsw) * 16), ag + i * 8);
            cp16(sB + lrow * 128 + ((c ^ lsw) * 16), bg + i * 8);
        }
        CP_COMMIT();
    }

    for (int kc = 0; kc < NK; kc++) {
        CP_WAIT1();
        __syncthreads();
        // issue next-next stage load (overlaps with compute below)
        if (kc + 2 < NK) {
            const int sp = (kc + 2) % 3;
            const uint32_t sA = base + sp * STG_BYTES;
            const uint32_t sB = sA + 128 * 128;
            const __nv_bfloat16* ag = Ab + (size_t)lrow * K + (kc + 2) * 64 + lc0 * 8;
            const __nv_bfloat16* bg = Bb + (size_t)lrow * K + (kc + 2) * 64 + lc0 * 8;
#pragma unroll
            for (int i = 0; i < 4; i++) {
                const int c = lc0 + i;
                cp16(sA + lrow * 128 + ((c ^ lsw) * 16), ag + i * 8);
                cp16(sB + lrow * 128 + ((c ^ lsw) * 16), bg + i * 8);
            }
        }
        CP_COMMIT();

        // compute on stage kc%3
        const uint32_t sA = base + (kc % 3) * STG_BYTES + (mw * 64) * 128;
        const uint32_t sB = base + (kc % 3) * STG_BYTES + 128 * 128 + (nw * 32) * 128;
        const int lr = lane & 15;
        const int lh = lane >> 4;
#pragma unroll
        for (int ks = 0; ks < 4; ks++) {
            const int ch = ks * 2 + lh;
            uint32_t a[4][4], bq[2][4];
#pragma unroll
            for (int mi = 0; mi < 4; mi++) {
                const int rr = mi * 16 + lr;
                ldm_x4(a[mi], sA + rr * 128 + ((ch ^ (rr & 7)) * 16));
            }
#pragma unroll
            for (int bi = 0; bi < 2; bi++) {
                const int rr = bi * 16 + lr;
                ldm_x4(bq[bi], sB + rr * 128 + ((ch ^ (rr & 7)) * 16));
            }
#pragma unroll
            for (int mi = 0; mi < 4; mi++)
#pragma unroll
                for (int ni = 0; ni < 4; ni++)
                    mma16816(acc[mi][ni], a[mi],
                             bq[ni >> 1][ni & 1], bq[ni >> 1][(ni & 1) + 2]);
        }
    }

    // Epilogue
    const float alpha = (EPI == 1) ? *alpha_p : 0.f;
    const int m0 = blockIdx.y * 128 + mw * 64;
    const int n0 = blockIdx.x * 128 + nw * 32;
    const int rl = lane >> 2;
    const int cl = (lane & 3) * 2;
#pragma unroll
    for (int mi = 0; mi < 4; mi++) {
#pragma unroll
        for (int e2 = 0; e2 < 2; e2++) {
            const int gr = m0 + mi * 16 + rl + e2 * 8;
#pragma unroll
            for (int ni = 0; ni < 4; ni++) {
                const int gc = n0 + ni * 8 + cl;
                float v0 = acc[mi][ni][e2 * 2];
                float v1 = acc[mi][ni][e2 * 2 + 1];
                if (EPI == 0) {
                    *(float2*)(Cf + (size_t)gr * N + gc) = make_float2(v0, v1);
                } else if (EPI == 1) {
                    const float2 bb = *(const float2*)(bias + gc);
                    const float2 rr = *(const float2*)(res + (size_t)gr * N + gc);
                    *(float2*)(Cf + (size_t)gr * N + gc) =
                        make_float2(rr.x + alpha * (v0 + bb.x),
                                    rr.y + alpha * (v1 + bb.y));
                } else {
                    const float2 bb = *(const float2*)(bias + gc);
                    *(uint32_t*)(Cb + (size_t)gr * N + gc) =
                        pk2(gelu_f(v0 + bb.x), gelu_f(v1 + bb.y));
                }
            }
        }
    }
}

// ---------------------------------------------------------------------------
// Flash attention, fp32 math, bf16 output. Block = one (b, h, 64-row q tile).
// 256 threads, online softmax over 32 kv tiles of 64. Scores / TAU (TAU=2).
// ---------------------------------------------------------------------------
#define ATTN_SMEM_BYTES ((4 * 64 * 68 + 3 * 64) * 4)

__global__ __launch_bounds__(256) void attn_kernel(
    const float* __restrict__ Q, const float* __restrict__ K,
    const float* __restrict__ V, __nv_bfloat16* __restrict__ O)
{
    extern __shared__ float sm[];
    float* Qs    = sm;
    float* Kst   = sm + 64 * 68;
    float* Vs    = sm + 2 * 64 * 68;
    float* Ss    = sm + 3 * 64 * 68;
    float* row_m = sm + 4 * 64 * 68;
    float* row_l = row_m + 64;
    float* row_c = row_l + 64;

    const int tid = threadIdx.x;
    const int tx = tid & 15;
    const int ty = tid >> 4;
    const int qt = blockIdx.x, h = blockIdx.y, b = blockIdx.z;

    const float* Qb = Q + ((size_t)(b * NLQ + qt * 64)) * NDIM + h * NHD;
    const float* Kb = K + ((size_t)b * NLKV) * NDIM + h * NHD;
    const float* Vb = V + ((size_t)b * NLKV) * NDIM + h * NHD;

#pragma unroll
    for (int it = 0; it < 4; it++) {
        const int idx = tid + it * 256;
        const int r = idx >> 4, c4 = idx & 15;
        *(float4*)&Qs[r * 68 + c4 * 4] = *(const float4*)&Qb[(size_t)r * NDIM + c4 * 4];
    }
    if (tid < 64) { row_m[tid] = -1e30f; row_l[tid] = 0.f; }

    float oacc[4][4];
#pragma unroll
    for (int i = 0; i < 4; i++)
#pragma unroll
        for (int j = 0; j < 4; j++) oacc[i][j] = 0.f;

    for (int kt = 0; kt < NLKV / 64; kt++) {
        __syncthreads();
#pragma unroll
        for (int it = 0; it < 4; it++) {
            const int idx = tid + it * 256;
            const int r = idx >> 4, c4 = idx & 15;
            const size_t grow = (size_t)(kt * 64 + r) * NDIM + c4 * 4;
            const float4 kk4 = *(const float4*)&Kb[grow];
            Kst[(c4 * 4 + 0) * 68 + r] = kk4.x;
            Kst[(c4 * 4 + 1) * 68 + r] = kk4.y;
            Kst[(c4 * 4 + 2) * 68 + r] = kk4.z;
            Kst[(c4 * 4 + 3) * 68 + r] = kk4.w;
            *(float4*)&Vs[r * 68 + c4 * 4] = *(const float4*)&Vb[grow];
        }
        __syncthreads();

        // S = Q K^T
        float s[4][4];
#pragma unroll
        for (int i = 0; i < 4; i++)
#pragma unroll
            for (int j = 0; j < 4; j++) s[i][j] = 0.f;
#pragma unroll
        for (int d4 = 0; d4 < 16; d4++) {
            float qr[4][4], kc[4][4];
#pragma unroll
            for (int u = 0; u < 4; u++) {
                const float4 t  = *(const float4*)&Qs [(ty * 4 + u) * 68 + d4 * 4];
                qr[u][0] = t.x; qr[u][1] = t.y; qr[u][2] = t.z; qr[u][3] = t.w;
                const float4 kk = *(const float4*)&Kst[(d4 * 4 + u) * 68 + tx * 4];
                kc[u][0] = kk.x; kc[u][1] = kk.y; kc[u][2] = kk.z; kc[u][3] = kk.w;
            }
#pragma unroll
            for (int i = 0; i < 4; i++)
#pragma unroll
                for (int dd = 0; dd < 4; dd++)
#pragma unroll
                    for (int j = 0; j < 4; j++)
                        s[i][j] = fmaf(qr[i][dd], kc[dd][j], s[i][j]);
        }
#pragma unroll
        for (int i = 0; i < 4; i++)
            *(float4*)&Ss[(ty * 4 + i) * 68 + tx * 4] =
                make_float4(s[i][0] * 0.5f, s[i][1] * 0.5f, s[i][2] * 0.5f, s[i][3] * 0.5f);
        __syncthreads();

        // Online softmax: 4 threads per q-row (all 256 threads active)
        {
            const int r  = tid >> 2;
            const int q4 = tid & 3;
            float* sr = &Ss[r * 68 + q4 * 16];
            const float mo = row_m[r];
            float lm = -1e30f;
#pragma unroll
            for (int j4 = 0; j4 < 4; j4++) {
                const float4 t = *(const float4*)&sr[j4 * 4];
                lm = fmaxf(lm, fmaxf(fmaxf(t.x, t.y), fmaxf(t.z, t.w)));
            }
            lm = fmaxf(lm, __shfl_xor_sync(0xffffffffu, lm, 1));
            lm = fmaxf(lm, __shfl_xor_sync(0xffffffffu, lm, 2));
            const float mt = fmaxf(mo, lm);
            float l = 0.f;
#pragma unroll
            for (int j4 = 0; j4 < 4; j4++) {
                float4 t = *(const float4*)&sr[j4 * 4];
                t.x = __expf(t.x - mt); t.y = __expf(t.y - mt);
                t.z = __expf(t.z - mt); t.w = __expf(t.w - mt);
                *(float4*)&sr[j4 * 4] = t;
                l += t.x + t.y + t.z + t.w;
            }
            l += __shfl_xor_sync(0xffffffffu, l, 1);
            l += __shfl_xor_sync(0xffffffffu, l, 2);
            if (q4 == 0) {
                const float c = __expf(mo - mt);
                row_c[r] = c;
                row_l[r] = row_l[r] * c + l;
                row_m[r] = mt;
            }
        }
        __syncthreads();

        {
            const float c0 = row_c[ty * 4 + 0], c1 = row_c[ty * 4 + 1];
            const float c2 = row_c[ty * 4 + 2], c3 = row_c[ty * 4 + 3];
#pragma unroll
            for (int j = 0; j < 4; j++) {
                oacc[0][j] *= c0; oacc[1][j] *= c1; oacc[2][j] *= c2; oacc[3][j] *= c3;
            }
        }

        // O += P V
#pragma unroll
        for (int k4 = 0; k4 < 16; k4++) {
            float pr[4][4], vc[4][4];
#pragma unroll
            for (int u = 0; u < 4; u++) {
                const float4 t  = *(const float4*)&Ss[(ty * 4 + u) * 68 + k4 * 4];
                pr[u][0] = t.x; pr[u][1] = t.y; pr[u][2] = t.z; pr[u][3] = t.w;
                const float4 vv = *(const float4*)&Vs[(k4 * 4 + u) * 68 + tx * 4];
                vc[u][0] = vv.x; vc[u][1] = vv.y; vc[u][2] = vv.z; vc[u][3] = vv.w;
            }
#pragma unroll
            for (int i = 0; i < 4; i++)
#pragma unroll
                for (int kk = 0; kk < 4; kk++)
#pragma unroll
                    for (int j = 0; j < 4; j++)
                        oacc[i][j] = fmaf(pr[i][kk], vc[kk][j], oacc[i][j]);
        }
    }

    __nv_bfloat16* Ob = O + ((size_t)(b * NLQ + qt * 64)) * NDIM + h * NHD;
#pragma unroll
    for (int i = 0; i < 4; i++) {
        const float inv = 1.f / row_l[ty * 4 + i];
        *(uint2*)&Ob[(size_t)(ty * 4 + i) * NDIM + tx * 4] =
            make_uint2(pk2(oacc[i][0] * inv, oacc[i][1] * inv),
                       pk2(oacc[i][2] * inv, oacc[i][3] * inv));
    }
}

// ---------------------------------------------------------------------------
// Launch
// ---------------------------------------------------------------------------
extern "C" void kernel_launch(void* const* d_in, const int* in_sizes, int n_in,
                              void* d_out, int out_size)
{
    (void)in_sizes; (void)n_in; (void)out_size;
    const float* q_tokens   = (const float*)d_in[0];
    const float* kv_tokens  = (const float*)d_in[1];
    const float* q_ln_w     = (const float*)d_in[2];
    const float* q_ln_b     = (const float*)d_in[3];
    const float* kv_ln_w    = (const float*)d_in[4];
    const float* kv_ln_b    = (const float*)d_in[5];
    const float* mlp_ln_w   = (const float*)d_in[6];
    const float* mlp_ln_b   = (const float*)d_in[7];
    const float* Wq         = (const float*)d_in[8];
    const float* Wk         = (const float*)d_in[9];
    const float* Wv         = (const float*)d_in[10];
    const float* Wo         = (const float*)d_in[11];
    const float* bo         = (const float*)d_in[12];
    const float* fc1_w      = (const float*)d_in[13];
    const float* fc1_b      = (const float*)d_in[14];
    const float* fc2_w      = (const float*)d_in[15];
    const float* fc2_b      = (const float*)d_in[16];
    const float* alpha_attn = (const float*)d_in[17];
    const float* alpha_mlp  = (const float*)d_in[18];
    float* out = (float*)d_out;

    void* p;
    __nv_bfloat16 *QNB, *KVNB, *CTXB, *HNB, *H1B, *WQB, *WKB, *WVB, *WOB, *F1B, *F2B;
    float *Qm, *Km, *Vm, *RES;
    cudaGetSymbolAddress(&p, g_qnb);  QNB  = (__nv_bfloat16*)p;
    cudaGetSymbolAddress(&p, g_kvnb); KVNB = (__nv_bfloat16*)p;
    cudaGetSymbolAddress(&p, g_ctxb); CTXB = (__nv_bfloat16*)p;
    cudaGetSymbolAddress(&p, g_hnb);  HNB  = (__nv_bfloat16*)p;
    cudaGetSymbolAddress(&p, g_h1b);  H1B  = (__nv_bfloat16*)p;
    cudaGetSymbolAddress(&p, g_wqb);  WQB  = (__nv_bfloat16*)p;
    cudaGetSymbolAddress(&p, g_wkb);  WKB  = (__nv_bfloat16*)p;
    cudaGetSymbolAddress(&p, g_wvb);  WVB  = (__nv_bfloat16*)p;
    cudaGetSymbolAddress(&p, g_wob);  WOB  = (__nv_bfloat16*)p;
    cudaGetSymbolAddress(&p, g_f1b);  F1B  = (__nv_bfloat16*)p;
    cudaGetSymbolAddress(&p, g_f2b);  F2B  = (__nv_bfloat16*)p;
    cudaGetSymbolAddress(&p, g_q);    Qm   = (float*)p;
    cudaGetSymbolAddress(&p, g_k);    Km   = (float*)p;
    cudaGetSymbolAddress(&p, g_v);    Vm   = (float*)p;
    cudaGetSymbolAddress(&p, g_res);  RES  = (float*)p;

    cudaFuncSetAttribute(gemm_mma<0>, cudaFuncAttributeMaxDynamicSharedMemorySize, GEMM_SMEM);
    cudaFuncSetAttribute(gemm_mma<1>, cudaFuncAttributeMaxDynamicSharedMemorySize, GEMM_SMEM);
    cudaFuncSetAttribute(gemm_mma<2>, cudaFuncAttributeMaxDynamicSharedMemorySize, GEMM_SMEM);
    cudaFuncSetAttribute(attn_kernel, cudaFuncAttributeMaxDynamicSharedMemorySize, ATTN_SMEM_BYTES);

    // Weight fp32 -> bf16
    conv_kernel<<<NDIM * NDIM / 1024, 256>>>(Wq, WQB);
    conv_kernel<<<NDIM * NDIM / 1024, 256>>>(Wk, WKB);
    conv_kernel<<<NDIM * NDIM / 1024, 256>>>(Wv, WVB);
    conv_kernel<<<NDIM * NDIM / 1024, 256>>>(Wo, WOB);
    conv_kernel<<<NMH * NDIM / 1024, 256>>>(fc1_w, F1B);
    conv_kernel<<<NDIM * NMH / 1024, 256>>>(fc2_w, F2B);

    // 1) LayerNorms -> bf16
    ln_bf16_kernel<<<MQ,  256>>>(q_tokens,  q_ln_w,  q_ln_b,  QNB);
    ln_bf16_kernel<<<MKV, 256>>>(kv_tokens, kv_ln_w, kv_ln_b, KVNB);

    // 2) Q/K/V projections (HMMA bf16, fp32 out)
    gemm_mma<0><<<dim3(NDIM/128, MQ/128),  256, GEMM_SMEM>>>(QNB,  WQB, nullptr, nullptr, nullptr, Qm, nullptr, MQ,  NDIM, NDIM);
    gemm_mma<0><<<dim3(NDIM/128, MKV/128), 256, GEMM_SMEM>>>(KVNB, WKB, nullptr, nullptr, nullptr, Km, nullptr, MKV, NDIM, NDIM);
    gemm_mma<0><<<dim3(NDIM/128, MKV/128), 256, GEMM_SMEM>>>(KVNB, WVB, nullptr, nullptr, nullptr, Vm, nullptr, MKV, NDIM, NDIM);

    // 3) Per-head L2 normalization of q and k
    l2norm_kernel<<<(MQ  * NH) / 8, 256>>>(Qm);
    l2norm_kernel<<<(MKV * NH) / 8, 256>>>(Km);

    // 4) Attention -> bf16 ctx
    attn_kernel<<<dim3(NLQ/64, NH, NB), 256, ATTN_SMEM_BYTES>>>(Qm, Km, Vm, CTXB);

    // 5) Output projection + attn residual (fp32 out)
    gemm_mma<1><<<dim3(NDIM/128, MQ/128), 256, GEMM_SMEM>>>(CTXB, WOB, bo, q_tokens, alpha_attn, RES, nullptr, MQ, NDIM, NDIM);

    // 6) MLP
    ln_bf16_kernel<<<MQ, 256>>>(RES, mlp_ln_w, mlp_ln_b, HNB);
    gemm_mma<2><<<dim3(NMH/128, MQ/128), 256, GEMM_SMEM>>>(HNB, F1B, fc1_b, nullptr, nullptr, nullptr, H1B, MQ, NMH, NDIM);
    gemm_mma<1><<<dim3(NDIM/128, MQ/128), 256, GEMM_SMEM>>>(H1B, F2B, fc2_b, RES, alpha_mlp, out, nullptr, MQ, NDIM, NMH);
}

// round 8
// speedup vs baseline: 4.9486x; 1.9426x over previous
#include <cuda_runtime.h>
#include <cuda_bf16.h>
#include <math.h>
#include <stdint.h>

// Problem constants
#define NB   4
#define NLQ  512
#define NLKV 2048
#define NDIM 1024
#define NH   16
#define NHD  64
#define NMH  4096

#define MQ  (NB * NLQ)    // 2048
#define MKV (NB * NLKV)   // 8192

// ---------------------------------------------------------------------------
// Scratch (device globals; no allocation allowed)
// ---------------------------------------------------------------------------
__device__ __align__(256) __nv_bfloat16 g_qnb [MQ  * NDIM];
__device__ __align__(256) __nv_bfloat16 g_kvnb[MKV * NDIM];
__device__ __align__(256) __nv_bfloat16 g_qb  [MQ  * NDIM];
__device__ __align__(256) __nv_bfloat16 g_kb  [MKV * NDIM];
__device__ __align__(256) __nv_bfloat16 g_vb  [MKV * NDIM];
__device__ __align__(256) __nv_bfloat16 g_ctxb[MQ  * NDIM];
__device__ __align__(256) __nv_bfloat16 g_hnb [MQ  * NDIM];
__device__ __align__(256) __nv_bfloat16 g_h1b [MQ  * NMH];
__device__ __align__(256) __nv_bfloat16 g_wqb [NDIM * NDIM];
__device__ __align__(256) __nv_bfloat16 g_wkb [NDIM * NDIM];
__device__ __align__(256) __nv_bfloat16 g_wvb [NDIM * NDIM];
__device__ __align__(256) __nv_bfloat16 g_wob [NDIM * NDIM];
__device__ __align__(256) __nv_bfloat16 g_f1b [NMH * NDIM];
__device__ __align__(256) __nv_bfloat16 g_f2b [NDIM * NMH];
__device__ __align__(256) float g_res[MQ * NDIM];

// ---------------------------------------------------------------------------
// PTX helpers (sm_80-era: cp.async, ldmatrix, mma.sync — legal on sm_103)
// ---------------------------------------------------------------------------
__device__ __forceinline__ uint32_t smem_u32(const void* p) {
    uint32_t a;
    asm("{ .reg .u64 t; cvta.to.shared.u64 t, %1; cvt.u32.u64 %0, t; }"
        : "=r"(a) : "l"(p));
    return a;
}

__device__ __forceinline__ void cp16(uint32_t dst, const void* src) {
    asm volatile("cp.async.cg.shared.global [%0], [%1], 16;" :: "r"(dst), "l"(src));
}
#define CP_COMMIT() asm volatile("cp.async.commit_group;" ::: "memory")
#define CP_WAIT1()  asm volatile("cp.async.wait_group 1;"  ::: "memory")
#define CP_WAIT0()  asm volatile("cp.async.wait_group 0;"  ::: "memory")

__device__ __forceinline__ void ldm_x4(uint32_t* r, uint32_t addr) {
    asm volatile("ldmatrix.sync.aligned.m8n8.x4.shared.b16 {%0,%1,%2,%3}, [%4];"
        : "=r"(r[0]), "=r"(r[1]), "=r"(r[2]), "=r"(r[3]) : "r"(addr));
}

__device__ __forceinline__ void ldm_x4_t(uint32_t* r, uint32_t addr) {
    asm volatile("ldmatrix.sync.aligned.m8n8.x4.trans.shared.b16 {%0,%1,%2,%3}, [%4];"
        : "=r"(r[0]), "=r"(r[1]), "=r"(r[2]), "=r"(r[3]) : "r"(addr));
}

__device__ __forceinline__ void mma16816(float* c, const uint32_t* a,
                                         uint32_t b0, uint32_t b1) {
    asm volatile(
        "mma.sync.aligned.m16n8k16.row.col.f32.bf16.bf16.f32 "
        "{%0,%1,%2,%3}, {%4,%5,%6,%7}, {%8,%9}, {%0,%1,%2,%3};"
        : "+f"(c[0]), "+f"(c[1]), "+f"(c[2]), "+f"(c[3])
        : "r"(a[0]), "r"(a[1]), "r"(a[2]), "r"(a[3]), "r"(b0), "r"(b1));
}

__device__ __forceinline__ uint32_t pk2(float a, float b) {
    return ((uint32_t)__bfloat16_as_ushort(__float2bfloat16(b)) << 16)
         |  (uint32_t)__bfloat16_as_ushort(__float2bfloat16(a));
}

__device__ __forceinline__ float gelu_f(float x) {
    return 0.5f * x * (1.0f + erff(x * 0.70710678118654752440f));
}

// ---------------------------------------------------------------------------
// fp32 -> bf16 conversion (4 elems/thread)
// ---------------------------------------------------------------------------
__global__ __launch_bounds__(256) void conv_kernel(
    const float* __restrict__ s, __nv_bfloat16* __restrict__ d)
{
    const int i = (blockIdx.x * 256 + threadIdx.x) * 4;
    const float4 v = *(const float4*)(s + i);
    *(uint2*)(d + i) = make_uint2(pk2(v.x, v.y), pk2(v.z, v.w));
}

// ---------------------------------------------------------------------------
// LayerNorm -> bf16 output. One block per row of 1024.
// ---------------------------------------------------------------------------
__global__ __launch_bounds__(256) void ln_bf16_kernel(
    const float* __restrict__ x, const float* __restrict__ w,
    const float* __restrict__ bp, __nv_bfloat16* __restrict__ y)
{
    const int row = blockIdx.x;
    const int tid = threadIdx.x;
    const float4 xv = *(const float4*)(x + (size_t)row * NDIM + tid * 4);
    float s  = xv.x + xv.y + xv.z + xv.w;
    float ss = fmaf(xv.x, xv.x, fmaf(xv.y, xv.y, fmaf(xv.z, xv.z, xv.w * xv.w)));

    __shared__ float rs[8], rss[8];
#pragma unroll
    for (int o = 16; o > 0; o >>= 1) {
        s  += __shfl_xor_sync(0xffffffffu, s,  o);
        ss += __shfl_xor_sync(0xffffffffu, ss, o);
    }
    if ((tid & 31) == 0) { rs[tid >> 5] = s; rss[tid >> 5] = ss; }
    __syncthreads();
    float st = 0.f, sst = 0.f;
#pragma unroll
    for (int i = 0; i < 8; i++) { st += rs[i]; sst += rss[i]; }

    const float mu  = st * (1.f / NDIM);
    const float var = sst * (1.f / NDIM) - mu * mu;
    const float inv = rsqrtf(var + 1e-6f);

    const float4 wv = *(const float4*)(w + tid * 4);
    const float4 bv = *(const float4*)(bp + tid * 4);
    float4 o;
    o.x = (xv.x - mu) * inv * wv.x + bv.x;
    o.y = (xv.y - mu) * inv * wv.y + bv.y;
    o.z = (xv.z - mu) * inv * wv.z + bv.z;
    o.w = (xv.w - mu) * inv * wv.w + bv.w;
    *(uint2*)(y + (size_t)row * NDIM + tid * 4) = make_uint2(pk2(o.x, o.y), pk2(o.z, o.w));
}

// ---------------------------------------------------------------------------
// Per-head L2 normalize, bf16 in-place. Rows of 64 bf16 (128B). 1 warp/row,
// 8 rows per 256-thread block.
// ---------------------------------------------------------------------------
__global__ __launch_bounds__(256) void l2norm_bf16_kernel(__nv_bfloat16* __restrict__ x)
{
    const int row  = blockIdx.x * 8 + (threadIdx.x >> 5);
    const int lane = threadIdx.x & 31;
    uint32_t* p = (uint32_t*)(x + (size_t)row * 64) + lane;
    const uint32_t u = *p;
    const float f0 = __bfloat162float(__ushort_as_bfloat16((unsigned short)(u & 0xffff)));
    const float f1 = __bfloat162float(__ushort_as_bfloat16((unsigned short)(u >> 16)));
    float ss = f0 * f0 + f1 * f1;
#pragma unroll
    for (int o = 16; o > 0; o >>= 1) ss += __shfl_xor_sync(0xffffffffu, ss, o);
    const float inv = 1.f / fmaxf(sqrtf(ss), 1e-6f);
    *p = pk2(f0 * inv, f1 * inv);
}

// ---------------------------------------------------------------------------
// mma.sync bf16 GEMM:  C[M,N] = A[M,K] @ B[N,K]^T   (A, B bf16, K-contiguous)
// BM=128, BN=128, BK=64, 3-stage cp.async pipeline, 256 threads (8 warps,
// 2x4 layout, 64x32 warp tiles), fp32 accumulators.
// EPI: 0 = fp32; 1 = fp32 res+alpha*(acc+bias); 2 = bf16 gelu(acc+bias); 3 = bf16
// ---------------------------------------------------------------------------
#define STG_BYTES (128 * 128 * 2)     // 32768 (A 16KB + B 16KB)
#define GEMM_SMEM (3 * STG_BYTES)     // 98304

template<int EPI>
__global__ __launch_bounds__(256) void gemm_mma(
    const __nv_bfloat16* __restrict__ A, const __nv_bfloat16* __restrict__ B,
    const float* __restrict__ bias, const float* __restrict__ res,
    const float* __restrict__ alpha_p,
    float* __restrict__ Cf, __nv_bfloat16* __restrict__ Cb,
    int M, int N, int K)
{
    extern __shared__ char dyn[];
    const uint32_t base = smem_u32(dyn);
    const int tid  = threadIdx.x;
    const int wid  = tid >> 5, lane = tid & 31;
    const int mw   = wid & 1;         // 0..1  (m dimension)
    const int nw   = wid >> 1;        // 0..3  (n dimension)

    const __nv_bfloat16* Ab = A + (size_t)blockIdx.y * 128 * K;
    const __nv_bfloat16* Bb = B + (size_t)blockIdx.x * 128 * K;
    const int NK = K / 64;

    const int lrow = tid >> 1;            // 0..127
    const int lc0  = (tid & 1) * 4;       // 0 or 4
    const int lsw  = lrow & 7;

    float acc[4][4][4];
#pragma unroll
    for (int mi = 0; mi < 4; mi++)
#pragma unroll
        for (int ni = 0; ni < 4; ni++)
#pragma unroll
            for (int e = 0; e < 4; e++) acc[mi][ni][e] = 0.f;

#pragma unroll
    for (int p = 0; p < 2; p++) {
        const uint32_t sA = base + p * STG_BYTES;
        const uint32_t sB = sA + 128 * 128;
        const __nv_bfloat16* ag = Ab + (size_t)lrow * K + p * 64 + lc0 * 8;
        const __nv_bfloat16* bg = Bb + (size_t)lrow * K + p * 64 + lc0 * 8;
#pragma unroll
        for (int i = 0; i < 4; i++) {
            const int c = lc0 + i;
            cp16(sA + lrow * 128 + ((c ^ lsw) * 16), ag + i * 8);
            cp16(sB + lrow * 128 + ((c ^ lsw) * 16), bg + i * 8);
        }
        CP_COMMIT();
    }

    for (int kc = 0; kc < NK; kc++) {
        CP_WAIT1();
        __syncthreads();
        if (kc + 2 < NK) {
            const int sp = (kc + 2) % 3;
            const uint32_t sA = base + sp * STG_BYTES;
            const uint32_t sB = sA + 128 * 128;
            const __nv_bfloat16* ag = Ab + (size_t)lrow * K + (kc + 2) * 64 + lc0 * 8;
            const __nv_bfloat16* bg = Bb + (size_t)lrow * K + (kc + 2) * 64 + lc0 * 8;
#pragma unroll
            for (int i = 0; i < 4; i++) {
                const int c = lc0 + i;
                cp16(sA + lrow * 128 + ((c ^ lsw) * 16), ag + i * 8);
                cp16(sB + lrow * 128 + ((c ^ lsw) * 16), bg + i * 8);
            }
        }
        CP_COMMIT();

        const uint32_t sA = base + (kc % 3) * STG_BYTES + (mw * 64) * 128;
        const uint32_t sB = base + (kc % 3) * STG_BYTES + 128 * 128 + (nw * 32) * 128;
        const int lr = lane & 15;
        const int lh = lane >> 4;
#pragma unroll
        for (int ks = 0; ks < 4; ks++) {
            const int ch = ks * 2 + lh;
            uint32_t a[4][4], bq[2][4];
#pragma unroll
            for (int mi = 0; mi < 4; mi++) {
                const int rr = mi * 16 + lr;
                ldm_x4(a[mi], sA + rr * 128 + ((ch ^ (rr & 7)) * 16));
            }
#pragma unroll
            for (int bi = 0; bi < 2; bi++) {
                const int rr = bi * 16 + lr;
                ldm_x4(bq[bi], sB + rr * 128 + ((ch ^ (rr & 7)) * 16));
            }
#pragma unroll
            for (int mi = 0; mi < 4; mi++)
#pragma unroll
                for (int ni = 0; ni < 4; ni++)
                    mma16816(acc[mi][ni], a[mi],
                             bq[ni >> 1][ni & 1], bq[ni >> 1][(ni & 1) + 2]);
        }
    }

    const float alpha = (EPI == 1) ? *alpha_p : 0.f;
    const int m0 = blockIdx.y * 128 + mw * 64;
    const int n0 = blockIdx.x * 128 + nw * 32;
    const int rl = lane >> 2;
    const int cl = (lane & 3) * 2;
#pragma unroll
    for (int mi = 0; mi < 4; mi++) {
#pragma unroll
        for (int e2 = 0; e2 < 2; e2++) {
            const int gr = m0 + mi * 16 + rl + e2 * 8;
#pragma unroll
            for (int ni = 0; ni < 4; ni++) {
                const int gc = n0 + ni * 8 + cl;
                float v0 = acc[mi][ni][e2 * 2];
                float v1 = acc[mi][ni][e2 * 2 + 1];
                if (EPI == 0) {
                    *(float2*)(Cf + (size_t)gr * N + gc) = make_float2(v0, v1);
                } else if (EPI == 1) {
                    const float2 bb = *(const float2*)(bias + gc);
                    const float2 rr = *(const float2*)(res + (size_t)gr * N + gc);
                    *(float2*)(Cf + (size_t)gr * N + gc) =
                        make_float2(rr.x + alpha * (v0 + bb.x),
                                    rr.y + alpha * (v1 + bb.y));
                } else if (EPI == 2) {
                    const float2 bb = *(const float2*)(bias + gc);
                    *(uint32_t*)(Cb + (size_t)gr * N + gc) =
                        pk2(gelu_f(v0 + bb.x), gelu_f(v1 + bb.y));
                } else {
                    *(uint32_t*)(Cb + (size_t)gr * N + gc) = pk2(v0, v1);
                }
            }
        }
    }
}

// ---------------------------------------------------------------------------
// Flash attention, bf16 mma.sync, register-resident online softmax.
// Block = (b, h, 128-row q tile), 256 threads (8 warps x 16 q rows).
// KV tiles of 64, double-buffered cp.async. Scores * 0.5 (1/TAU).
// SMEM: Q 16KB + 2 stages x (K 8KB + V 8KB) = 48KB.
// ---------------------------------------------------------------------------
#define AT_SMEM 49152

__global__ __launch_bounds__(256) void attn_mma(
    const __nv_bfloat16* __restrict__ Q, const __nv_bfloat16* __restrict__ K,
    const __nv_bfloat16* __restrict__ V, __nv_bfloat16* __restrict__ O)
{
    extern __shared__ char smc[];
    const uint32_t Qs  = smem_u32(smc);
    const uint32_t KV0 = Qs + 16384;

    const int tid = threadIdx.x, wid = tid >> 5, lane = tid & 31;
    const int qt = blockIdx.x, h = blockIdx.y, b = blockIdx.z;

    const __nv_bfloat16* Qg = Q + ((size_t)(b * NLQ + qt * 128)) * NDIM + h * NHD;
    const __nv_bfloat16* Kg = K + ((size_t)b * NLKV) * NDIM + h * NHD;
    const __nv_bfloat16* Vg = V + ((size_t)b * NLKV) * NDIM + h * NHD;

    // Q tile: 128 rows x 128B, swizzled
    {
        const int r = tid >> 1, c0 = (tid & 1) * 4;
#pragma unroll
        for (int i = 0; i < 4; i++) {
            const int c = c0 + i;
            cp16(Qs + r * 128 + ((c ^ (r & 7)) * 16), Qg + (size_t)r * NDIM + c * 8);
        }
    }
    CP_COMMIT();
    // KV tile 0 -> stage 0
    {
        const int r = tid >> 2, c0 = (tid & 3) * 2;
#pragma unroll
        for (int i = 0; i < 2; i++) {
            const int c = c0 + i;
            const uint32_t so = r * 128 + ((c ^ (r & 7)) * 16);
            cp16(KV0 + so, Kg + (size_t)r * NDIM + c * 8);
            cp16(KV0 + 8192 + so, Vg + (size_t)r * NDIM + c * 8);
        }
    }
    CP_COMMIT();
    CP_WAIT1();   // Q resident
    __syncthreads();

    // Q fragments (A operand), kept for the whole KV loop
    uint32_t qa[4][4];
    const int lr = lane & 15, lh = lane >> 4;
#pragma unroll
    for (int ks = 0; ks < 4; ks++) {
        const int rr = wid * 16 + lr, ch = ks * 2 + lh;
        ldm_x4(qa[ks], Qs + rr * 128 + ((ch ^ (rr & 7)) * 16));
    }

    float oc[8][4];
#pragma unroll
    for (int dj = 0; dj < 8; dj++)
#pragma unroll
        for (int e = 0; e < 4; e++) oc[dj][e] = 0.f;
    float m0 = -1e30f, m1 = -1e30f, l0 = 0.f, l1 = 0.f;

    for (int kt = 0; kt < NLKV / 64; kt++) {
        __syncthreads();  // everyone done reading the stage about to be overwritten
        if (kt + 1 < NLKV / 64) {
            const uint32_t st = KV0 + ((kt + 1) & 1) * 16384;
            const int r = tid >> 2, c0 = (tid & 3) * 2;
            const __nv_bfloat16* kg = Kg + (size_t)((kt + 1) * 64 + r) * NDIM;
            const __nv_bfloat16* vg = Vg + (size_t)((kt + 1) * 64 + r) * NDIM;
#pragma unroll
            for (int i = 0; i < 2; i++) {
                const int c = c0 + i;
                const uint32_t so = r * 128 + ((c ^ (r & 7)) * 16);
                cp16(st + so, kg + c * 8);
                cp16(st + 8192 + so, vg + c * 8);
            }
            CP_COMMIT();
            CP_WAIT1();
        } else {
            CP_WAIT0();
        }
        __syncthreads();

        const uint32_t Kb = KV0 + (kt & 1) * 16384;
        const uint32_t Vb = Kb + 8192;

        // S = Q K^T  (warp: 16 q rows x 64 kv cols)
        float sc[8][4];
#pragma unroll
        for (int ni = 0; ni < 8; ni++)
#pragma unroll
            for (int e = 0; e < 4; e++) sc[ni][e] = 0.f;
#pragma unroll
        for (int ks = 0; ks < 4; ks++) {
            uint32_t bq[4][4];
            const int ch = ks * 2 + lh;
#pragma unroll
            for (int bi = 0; bi < 4; bi++) {
                const int rr = bi * 16 + lr;
                ldm_x4(bq[bi], Kb + rr * 128 + ((ch ^ (rr & 7)) * 16));
            }
#pragma unroll
            for (int ni = 0; ni < 8; ni++)
                mma16816(sc[ni], qa[ks], bq[ni >> 1][ni & 1], bq[ni >> 1][(ni & 1) + 2]);
        }

        // scale + register-resident online softmax (rows lane>>2 and +8)
        float nm0 = -1e30f, nm1 = -1e30f;
#pragma unroll
        for (int ni = 0; ni < 8; ni++) {
            sc[ni][0] *= 0.5f; sc[ni][1] *= 0.5f; sc[ni][2] *= 0.5f; sc[ni][3] *= 0.5f;
            nm0 = fmaxf(nm0, fmaxf(sc[ni][0], sc[ni][1]));
            nm1 = fmaxf(nm1, fmaxf(sc[ni][2], sc[ni][3]));
        }
        nm0 = fmaxf(nm0, __shfl_xor_sync(0xffffffffu, nm0, 1));
        nm0 = fmaxf(nm0, __shfl_xor_sync(0xffffffffu, nm0, 2));
        nm1 = fmaxf(nm1, __shfl_xor_sync(0xffffffffu, nm1, 1));
        nm1 = fmaxf(nm1, __shfl_xor_sync(0xffffffffu, nm1, 2));
        const float mt0 = fmaxf(m0, nm0), mt1 = fmaxf(m1, nm1);
        const float c0 = __expf(m0 - mt0), c1 = __expf(m1 - mt1);
        m0 = mt0; m1 = mt1;
        float s0 = 0.f, s1 = 0.f;
#pragma unroll
        for (int ni = 0; ni < 8; ni++) {
            sc[ni][0] = __expf(sc[ni][0] - mt0);
            sc[ni][1] = __expf(sc[ni][1] - mt0);
            sc[ni][2] = __expf(sc[ni][2] - mt1);
            sc[ni][3] = __expf(sc[ni][3] - mt1);
            s0 += sc[ni][0] + sc[ni][1];
            s1 += sc[ni][2] + sc[ni][3];
        }
        s0 += __shfl_xor_sync(0xffffffffu, s0, 1);
        s0 += __shfl_xor_sync(0xffffffffu, s0, 2);
        s1 += __shfl_xor_sync(0xffffffffu, s1, 1);
        s1 += __shfl_xor_sync(0xffffffffu, s1, 2);
        l0 = l0 * c0 + s0;
        l1 = l1 * c1 + s1;
#pragma unroll
        for (int dj = 0; dj < 8; dj++) {
            oc[dj][0] *= c0; oc[dj][1] *= c0; oc[dj][2] *= c1; oc[dj][3] *= c1;
        }

        // O += P V  (P accumulators re-used as A fragments; V via ldmatrix.trans)
#pragma unroll
        for (int t = 0; t < 4; t++) {
            uint32_t pa[4];
            pa[0] = pk2(sc[2 * t][0],     sc[2 * t][1]);
            pa[1] = pk2(sc[2 * t][2],     sc[2 * t][3]);
            pa[2] = pk2(sc[2 * t + 1][0], sc[2 * t + 1][1]);
            pa[3] = pk2(sc[2 * t + 1][2], sc[2 * t + 1][3]);
            const int rr = t * 16 + (lane & 7) + ((lane >> 3) & 1) * 8;
#pragma unroll
            for (int dj2 = 0; dj2 < 4; dj2++) {
                const int cc = dj2 * 2 + lh;
                uint32_t vb[4];
                ldm_x4_t(vb, Vb + rr * 128 + ((cc ^ (rr & 7)) * 16));
                mma16816(oc[dj2 * 2],     pa, vb[0], vb[1]);
                mma16816(oc[dj2 * 2 + 1], pa, vb[2], vb[3]);
            }
        }
    }

    const float i0 = 1.f / l0, i1 = 1.f / l1;
    __nv_bfloat16* Ob = O + ((size_t)(b * NLQ + qt * 128 + wid * 16 + (lane >> 2))) * NDIM
                          + h * NHD + (lane & 3) * 2;
#pragma unroll
    for (int dj = 0; dj < 8; dj++) {
        *(uint32_t*)(Ob + dj * 8)            = pk2(oc[dj][0] * i0, oc[dj][1] * i0);
        *(uint32_t*)(Ob + 8 * NDIM + dj * 8) = pk2(oc[dj][2] * i1, oc[dj][3] * i1);
    }
}

// ---------------------------------------------------------------------------
// Launch
// ---------------------------------------------------------------------------
extern "C" void kernel_launch(void* const* d_in, const int* in_sizes, int n_in,
                              void* d_out, int out_size)
{
    (void)in_sizes; (void)n_in; (void)out_size;
    const float* q_tokens   = (const float*)d_in[0];
    const float* kv_tokens  = (const float*)d_in[1];
    const float* q_ln_w     = (const float*)d_in[2];
    const float* q_ln_b     = (const float*)d_in[3];
    const float* kv_ln_w    = (const float*)d_in[4];
    const float* kv_ln_b    = (const float*)d_in[5];
    const float* mlp_ln_w   = (const float*)d_in[6];
    const float* mlp_ln_b   = (const float*)d_in[7];
    const float* Wq         = (const float*)d_in[8];
    const float* Wk         = (const float*)d_in[9];
    const float* Wv         = (const float*)d_in[10];
    const float* Wo         = (const float*)d_in[11];
    const float* bo         = (const float*)d_in[12];
    const float* fc1_w      = (const float*)d_in[13];
    const float* fc1_b      = (const float*)d_in[14];
    const float* fc2_w      = (const float*)d_in[15];
    const float* fc2_b      = (const float*)d_in[16];
    const float* alpha_attn = (const float*)d_in[17];
    const float* alpha_mlp  = (const float*)d_in[18];
    float* out = (float*)d_out;

    void* p;
    __nv_bfloat16 *QNB, *KVNB, *QB, *KB, *VB, *CTXB, *HNB, *H1B;
    __nv_bfloat16 *WQB, *WKB, *WVB, *WOB, *F1B, *F2B;
    float *RES;
    cudaGetSymbolAddress(&p, g_qnb);  QNB  = (__nv_bfloat16*)p;
    cudaGetSymbolAddress(&p, g_kvnb); KVNB = (__nv_bfloat16*)p;
    cudaGetSymbolAddress(&p, g_qb);   QB   = (__nv_bfloat16*)p;
    cudaGetSymbolAddress(&p, g_kb);   KB   = (__nv_bfloat16*)p;
    cudaGetSymbolAddress(&p, g_vb);   VB   = (__nv_bfloat16*)p;
    cudaGetSymbolAddress(&p, g_ctxb); CTXB = (__nv_bfloat16*)p;
    cudaGetSymbolAddress(&p, g_hnb);  HNB  = (__nv_bfloat16*)p;
    cudaGetSymbolAddress(&p, g_h1b);  H1B  = (__nv_bfloat16*)p;
    cudaGetSymbolAddress(&p, g_wqb);  WQB  = (__nv_bfloat16*)p;
    cudaGetSymbolAddress(&p, g_wkb);  WKB  = (__nv_bfloat16*)p;
    cudaGetSymbolAddress(&p, g_wvb);  WVB  = (__nv_bfloat16*)p;
    cudaGetSymbolAddress(&p, g_wob);  WOB  = (__nv_bfloat16*)p;
    cudaGetSymbolAddress(&p, g_f1b);  F1B  = (__nv_bfloat16*)p;
    cudaGetSymbolAddress(&p, g_f2b);  F2B  = (__nv_bfloat16*)p;
    cudaGetSymbolAddress(&p, g_res);  RES  = (float*)p;

    cudaFuncSetAttribute(gemm_mma<0>, cudaFuncAttributeMaxDynamicSharedMemorySize, GEMM_SMEM);
    cudaFuncSetAttribute(gemm_mma<1>, cudaFuncAttributeMaxDynamicSharedMemorySize, GEMM_SMEM);
    cudaFuncSetAttribute(gemm_mma<2>, cudaFuncAttributeMaxDynamicSharedMemorySize, GEMM_SMEM);
    cudaFuncSetAttribute(gemm_mma<3>, cudaFuncAttributeMaxDynamicSharedMemorySize, GEMM_SMEM);
    cudaFuncSetAttribute(attn_mma,    cudaFuncAttributeMaxDynamicSharedMemorySize, AT_SMEM);

    // Weight fp32 -> bf16
    conv_kernel<<<NDIM * NDIM / 1024, 256>>>(Wq, WQB);
    conv_kernel<<<NDIM * NDIM / 1024, 256>>>(Wk, WKB);
    conv_kernel<<<NDIM * NDIM / 1024, 256>>>(Wv, WVB);
    conv_kernel<<<NDIM * NDIM / 1024, 256>>>(Wo, WOB);
    conv_kernel<<<NMH * NDIM / 1024, 256>>>(fc1_w, F1B);
    conv_kernel<<<NDIM * NMH / 1024, 256>>>(fc2_w, F2B);

    // 1) LayerNorms -> bf16
    ln_bf16_kernel<<<MQ,  256>>>(q_tokens,  q_ln_w,  q_ln_b,  QNB);
    ln_bf16_kernel<<<MKV, 256>>>(kv_tokens, kv_ln_w, kv_ln_b, KVNB);

    // 2) Q/K/V projections (HMMA bf16 -> bf16 out)
    gemm_mma<3><<<dim3(NDIM/128, MQ/128),  256, GEMM_SMEM>>>(QNB,  WQB, nullptr, nullptr, nullptr, nullptr, QB, MQ,  NDIM, NDIM);
    gemm_mma<3><<<dim3(NDIM/128, MKV/128), 256, GEMM_SMEM>>>(KVNB, WKB, nullptr, nullptr, nullptr, nullptr, KB, MKV, NDIM, NDIM);
    gemm_mma<3><<<dim3(NDIM/128, MKV/128), 256, GEMM_SMEM>>>(KVNB, WVB, nullptr, nullptr, nullptr, nullptr, VB, MKV, NDIM, NDIM);

    // 3) Per-head L2 normalization of q and k (bf16 in-place)
    l2norm_bf16_kernel<<<(MQ  * NH) / 8, 256>>>(QB);
    l2norm_bf16_kernel<<<(MKV * NH) / 8, 256>>>(KB);

    // 4) Attention (HMMA) -> bf16 ctx
    attn_mma<<<dim3(NLQ/128, NH, NB), 256, AT_SMEM>>>(QB, KB, VB, CTXB);

    // 5) Output projection + attn residual (fp32 out)
    gemm_mma<1><<<dim3(NDIM/128, MQ/128), 256, GEMM_SMEM>>>(CTXB, WOB, bo, q_tokens, alpha_attn, RES, nullptr, MQ, NDIM, NDIM);

    // 6) MLP
    ln_bf16_kernel<<<MQ, 256>>>(RES, mlp_ln_w, mlp_ln_b, HNB);
    gemm_mma<2><<<dim3(NMH/128, MQ/128), 256, GEMM_SMEM>>>(HNB, F1B, fc1_b, nullptr, nullptr, nullptr, H1B, MQ, NMH, NDIM);
    gemm_mma<1><<<dim3(NDIM/128, MQ/128), 256, GEMM_SMEM>>>(H1B, F2B, fc2_b, RES, alpha_mlp, out, nullptr, MQ, NDIM, NMH);
}

// round 11
// speedup vs baseline: 5.1551x; 1.0417x over previous
#include <cuda_runtime.h>
#include <cuda_bf16.h>
#include <math.h>
#include <stdint.h>

// Problem constants
#define NB   4
#define NLQ  512
#define NLKV 2048
#define NDIM 1024
#define NH   16
#define NHD  64
#define NMH  4096

#define MQ  (NB * NLQ)    // 2048
#define MKV (NB * NLKV)   // 8192
#define KVW 2048          // fused KV output width

// ---------------------------------------------------------------------------
// Scratch (device globals; no allocation allowed)
// ---------------------------------------------------------------------------
__device__ __align__(256) __nv_bfloat16 g_qnb [MQ  * NDIM];
__device__ __align__(256) __nv_bfloat16 g_kvnb[MKV * NDIM];
__device__ __align__(256) __nv_bfloat16 g_qb  [MQ  * NDIM];
__device__ __align__(256) __nv_bfloat16 g_kvb [MKV * KVW];   // [K | V] fused
__device__ __align__(256) __nv_bfloat16 g_ctxb[MQ  * NDIM];
__device__ __align__(256) __nv_bfloat16 g_hnb [MQ  * NDIM];
__device__ __align__(256) __nv_bfloat16 g_h1b [MQ  * NMH];
__device__ __align__(256) __nv_bfloat16 g_wqb [NDIM * NDIM];
__device__ __align__(256) __nv_bfloat16 g_wkvb[KVW  * NDIM];  // rows: Wk then Wv
__device__ __align__(256) __nv_bfloat16 g_wob [NDIM * NDIM];
__device__ __align__(256) __nv_bfloat16 g_f1b [NMH * NDIM];
__device__ __align__(256) __nv_bfloat16 g_f2b [NDIM * NMH];
__device__ __align__(256) float g_res[MQ * NDIM];

// ---------------------------------------------------------------------------
// PTX helpers
// ---------------------------------------------------------------------------
__device__ __forceinline__ uint32_t smem_u32(const void* p) {
    uint32_t a;
    asm("{ .reg .u64 t; cvta.to.shared.u64 t, %1; cvt.u32.u64 %0, t; }"
        : "=r"(a) : "l"(p));
    return a;
}

__device__ __forceinline__ void cp16(uint32_t dst, const void* src) {
    asm volatile("cp.async.cg.shared.global [%0], [%1], 16;" :: "r"(dst), "l"(src));
}
#define CP_COMMIT() asm volatile("cp.async.commit_group;" ::: "memory")
#define CP_WAIT1()  asm volatile("cp.async.wait_group 1;"  ::: "memory")
#define CP_WAIT0()  asm volatile("cp.async.wait_group 0;"  ::: "memory")

__device__ __forceinline__ void ldm_x4(uint32_t* r, uint32_t addr) {
    asm volatile("ldmatrix.sync.aligned.m8n8.x4.shared.b16 {%0,%1,%2,%3}, [%4];"
        : "=r"(r[0]), "=r"(r[1]), "=r"(r[2]), "=r"(r[3]) : "r"(addr));
}

__device__ __forceinline__ void ldm_x4_t(uint32_t* r, uint32_t addr) {
    asm volatile("ldmatrix.sync.aligned.m8n8.x4.trans.shared.b16 {%0,%1,%2,%3}, [%4];"
        : "=r"(r[0]), "=r"(r[1]), "=r"(r[2]), "=r"(r[3]) : "r"(addr));
}

__device__ __forceinline__ void mma16816(float* c, const uint32_t* a,
                                         uint32_t b0, uint32_t b1) {
    asm volatile(
        "mma.sync.aligned.m16n8k16.row.col.f32.bf16.bf16.f32 "
        "{%0,%1,%2,%3}, {%4,%5,%6,%7}, {%8,%9}, {%0,%1,%2,%3};"
        : "+f"(c[0]), "+f"(c[1]), "+f"(c[2]), "+f"(c[3])
        : "r"(a[0]), "r"(a[1]), "r"(a[2]), "r"(a[3]), "r"(b0), "r"(b1));
}

__device__ __forceinline__ uint32_t pk2(float a, float b) {
    return ((uint32_t)__bfloat16_as_ushort(__float2bfloat16(b)) << 16)
         |  (uint32_t)__bfloat16_as_ushort(__float2bfloat16(a));
}

__device__ __forceinline__ float gelu_f(float x) {
    return 0.5f * x * (1.0f + erff(x * 0.70710678118654752440f));
}

// ---------------------------------------------------------------------------
// Fused weight conversion: all 6 weight matrices, one launch.
// Segments (1024 elems per block): Wq 1024, Wk 1024, Wv 1024, Wo 1024,
// fc1 4096, fc2 4096 blocks -> total 12288.
// Wk/Wv interleave into g_wkvb rows [0,1024) / [1024,2048).
// ---------------------------------------------------------------------------
__global__ __launch_bounds__(256) void conv6_kernel(
    const float* __restrict__ wq, const float* __restrict__ wk,
    const float* __restrict__ wv, const float* __restrict__ wo,
    const float* __restrict__ f1, const float* __restrict__ f2,
    __nv_bfloat16* __restrict__ dq, __nv_bfloat16* __restrict__ dkv,
    __nv_bfloat16* __restrict__ dwo, __nv_bfloat16* __restrict__ df1,
    __nv_bfloat16* __restrict__ df2)
{
    const int b = blockIdx.x;
    const float* s; __nv_bfloat16* d; int lb;
    if      (b < 1024) { s = wq; d = dq;                 lb = b; }
    else if (b < 2048) { s = wk; d = dkv;                lb = b - 1024; }
    else if (b < 3072) { s = wv; d = dkv + 1024 * NDIM;  lb = b - 2048; }
    else if (b < 4096) { s = wo; d = dwo;                lb = b - 3072; }
    else if (b < 8192) { s = f1; d = df1;                lb = b - 4096; }
    else               { s = f2; d = df2;                lb = b - 8192; }
    const int i = lb * 1024 + threadIdx.x * 4;
    const float4 v = *(const float4*)(s + i);
    *(uint2*)(d + i) = make_uint2(pk2(v.x, v.y), pk2(v.z, v.w));
}

// ---------------------------------------------------------------------------
// LayerNorm -> bf16. Dual-input variant: rows [0,MQ) from q stream,
// rows [MQ, MQ+MKV) from kv stream. One block per row of 1024.
// ---------------------------------------------------------------------------
__device__ __forceinline__ void ln_row(
    const float* __restrict__ x, const float* __restrict__ w,
    const float* __restrict__ bp, __nv_bfloat16* __restrict__ y, int row)
{
    const int tid = threadIdx.x;
    const float4 xv = *(const float4*)(x + (size_t)row * NDIM + tid * 4);
    float s  = xv.x + xv.y + xv.z + xv.w;
    float ss = fmaf(xv.x, xv.x, fmaf(xv.y, xv.y, fmaf(xv.z, xv.z, xv.w * xv.w)));

    __shared__ float rs[8], rss[8];
#pragma unroll
    for (int o = 16; o > 0; o >>= 1) {
        s  += __shfl_xor_sync(0xffffffffu, s,  o);
        ss += __shfl_xor_sync(0xffffffffu, ss, o);
    }
    if ((tid & 31) == 0) { rs[tid >> 5] = s; rss[tid >> 5] = ss; }
    __syncthreads();
    float st = 0.f, sst = 0.f;
#pragma unroll
    for (int i = 0; i < 8; i++) { st += rs[i]; sst += rss[i]; }

    const float mu  = st * (1.f / NDIM);
    const float var = sst * (1.f / NDIM) - mu * mu;
    const float inv = rsqrtf(var + 1e-6f);

    const float4 wv = *(const float4*)(w + tid * 4);
    const float4 bv = *(const float4*)(bp + tid * 4);
    float4 o;
    o.x = (xv.x - mu) * inv * wv.x + bv.x;
    o.y = (xv.y - mu) * inv * wv.y + bv.y;
    o.z = (xv.z - mu) * inv * wv.z + bv.z;
    o.w = (xv.w - mu) * inv * wv.w + bv.w;
    *(uint2*)(y + (size_t)row * NDIM + tid * 4) = make_uint2(pk2(o.x, o.y), pk2(o.z, o.w));
}

__global__ __launch_bounds__(256) void ln2_kernel(
    const float* __restrict__ qx, const float* __restrict__ qw,
    const float* __restrict__ qb, __nv_bfloat16* __restrict__ qy,
    const float* __restrict__ kx, const float* __restrict__ kw,
    const float* __restrict__ kb, __nv_bfloat16* __restrict__ ky)
{
    const int row = blockIdx.x;
    if (row < MQ) ln_row(qx, qw, qb, qy, row);
    else          ln_row(kx, kw, kb, ky, row - MQ);
}

__global__ __launch_bounds__(256) void ln_bf16_kernel(
    const float* __restrict__ x, const float* __restrict__ w,
    const float* __restrict__ bp, __nv_bfloat16* __restrict__ y)
{
    ln_row(x, w, bp, y, blockIdx.x);
}

// ---------------------------------------------------------------------------
// Per-head L2 normalize, bf16 in-place. head-row hr -> token hr/16, head hr%16,
// 64 bf16 at token*ldc + h*64. 1 warp/head-row, 8 per block.
// ---------------------------------------------------------------------------
__global__ __launch_bounds__(256) void l2norm_bf16_kernel(
    __nv_bfloat16* __restrict__ x, int ldc)
{
    const int hr   = blockIdx.x * 8 + (threadIdx.x >> 5);
    const int lane = threadIdx.x & 31;
    const int token = hr >> 4, h = hr & 15;
    uint32_t* p = (uint32_t*)(x + (size_t)token * ldc + h * 64) + lane;
    const uint32_t u = *p;
    const float f0 = __bfloat162float(__ushort_as_bfloat16((unsigned short)(u & 0xffff)));
    const float f1 = __bfloat162float(__ushort_as_bfloat16((unsigned short)(u >> 16)));
    float ss = f0 * f0 + f1 * f1;
#pragma unroll
    for (int o = 16; o > 0; o >>= 1) ss += __shfl_xor_sync(0xffffffffu, ss, o);
    const float inv = 1.f / fmaxf(sqrtf(ss), 1e-6f);
    *p = pk2(f0 * inv, f1 * inv);
}

// ---------------------------------------------------------------------------
// mma.sync bf16 GEMM:  C[M,N] = A[M,K] @ B[N,K]^T
// BM=128, BN=128 or 256, BK=64, 3-stage cp.async pipeline, 256 threads
// (8 warps, 2 x 4 layout, warp tile 64 x (BN/4)), fp32 accumulators.
// EPI: 0 fp32; 1 fp32 res+alpha*(acc+bias); 2 bf16 gelu(acc+bias); 3 bf16
// ---------------------------------------------------------------------------
template<int EPI, int BN>
__global__ __launch_bounds__(256) void gemm_mma(
    const __nv_bfloat16* __restrict__ A, const __nv_bfloat16* __restrict__ B,
    const float* __restrict__ bias, const float* __restrict__ res,
    const float* __restrict__ alpha_p,
    float* __restrict__ Cf, __nv_bfloat16* __restrict__ Cb,
    int M, int N, int K)
{
    constexpr int WN   = BN / 4;        // warp tile N: 32 or 64
    constexpr int NI   = WN / 8;        // 4 or 8
    constexpr int NBL  = WN / 16;       // B ldmatrix count: 2 or 4
    constexpr int STGB = (128 + BN) * 128;

    extern __shared__ char dyn[];
    const uint32_t base = smem_u32(dyn);
    const int tid  = threadIdx.x;
    const int wid  = tid >> 5, lane = tid & 31;
    const int mw   = wid & 1;
    const int nw   = wid >> 1;

    const __nv_bfloat16* Ab = A + (size_t)blockIdx.y * 128 * K;
    const __nv_bfloat16* Bb = B + (size_t)blockIdx.x * BN * K;
    const int NK = K / 64;

    const int lrow = tid >> 1;
    const int lc0  = (tid & 1) * 4;

    float acc[4][NI][4];
#pragma unroll
    for (int mi = 0; mi < 4; mi++)
#pragma unroll
        for (int ni = 0; ni < NI; ni++)
#pragma unroll
            for (int e = 0; e < 4; e++) acc[mi][ni][e] = 0.f;

    // stage loader: A 128 rows + B BN rows, 128B each, XOR swizzle
#define LOAD_STAGE(sp, kchunk)                                                 \
    do {                                                                       \
        const uint32_t sA = base + (sp) * STGB;                                \
        const uint32_t sB = sA + 128 * 128;                                    \
        const __nv_bfloat16* ag = Ab + (size_t)lrow * K + (kchunk) * 64 + lc0 * 8; \
        _Pragma("unroll")                                                      \
        for (int i = 0; i < 4; i++) {                                          \
            const int c = lc0 + i;                                             \
            cp16(sA + lrow * 128 + ((c ^ (lrow & 7)) * 16), ag + i * 8);       \
        }                                                                      \
        _Pragma("unroll")                                                      \
        for (int rb = 0; rb < BN; rb += 128) {                                 \
            const int br = lrow + rb;                                          \
            const __nv_bfloat16* bg = Bb + (size_t)br * K + (kchunk) * 64 + lc0 * 8; \
            _Pragma("unroll")                                                  \
            for (int i = 0; i < 4; i++) {                                      \
                const int c = lc0 + i;                                         \
                cp16(sB + br * 128 + ((c ^ (br & 7)) * 16), bg + i * 8);       \
            }                                                                  \
        }                                                                      \
    } while (0)

#pragma unroll
    for (int p = 0; p < 2; p++) {
        LOAD_STAGE(p, p);
        CP_COMMIT();
    }

    for (int kc = 0; kc < NK; kc++) {
        CP_WAIT1();
        __syncthreads();
        if (kc + 2 < NK) {
            LOAD_STAGE((kc + 2) % 3, kc + 2);
        }
        CP_COMMIT();

        const uint32_t sA = base + (kc % 3) * STGB + (mw * 64) * 128;
        const uint32_t sB = base + (kc % 3) * STGB + 128 * 128 + (nw * WN) * 128;
        const int lr = lane & 15;
        const int lh = lane >> 4;
#pragma unroll
        for (int ks = 0; ks < 4; ks++) {
            const int ch = ks * 2 + lh;
            uint32_t a[4][4], bq[NBL][4];
#pragma unroll
            for (int mi = 0; mi < 4; mi++) {
                const int rr = mi * 16 + lr;
                ldm_x4(a[mi], sA + rr * 128 + ((ch ^ (rr & 7)) * 16));
            }
#pragma unroll
            for (int bi = 0; bi < NBL; bi++) {
                const int rr = bi * 16 + lr;
                ldm_x4(bq[bi], sB + rr * 128 + ((ch ^ (rr & 7)) * 16));
            }
#pragma unroll
            for (int mi = 0; mi < 4; mi++)
#pragma unroll
                for (int ni = 0; ni < NI; ni++)
                    mma16816(acc[mi][ni], a[mi],
                             bq[ni >> 1][ni & 1], bq[ni >> 1][(ni & 1) + 2]);
        }
    }
#undef LOAD_STAGE

    const float alpha = (EPI == 1) ? *alpha_p : 0.f;
    const int m0 = blockIdx.y * 128 + mw * 64;
    const int n0 = blockIdx.x * BN + nw * WN;
    const int rl = lane >> 2;
    const int cl = (lane & 3) * 2;
#pragma unroll
    for (int mi = 0; mi < 4; mi++) {
#pragma unroll
        for (int e2 = 0; e2 < 2; e2++) {
            const int gr = m0 + mi * 16 + rl + e2 * 8;
#pragma unroll
            for (int ni = 0; ni < NI; ni++) {
                const int gc = n0 + ni * 8 + cl;
                float v0 = acc[mi][ni][e2 * 2];
                float v1 = acc[mi][ni][e2 * 2 + 1];
                if (EPI == 0) {
                    *(float2*)(Cf + (size_t)gr * N + gc) = make_float2(v0, v1);
                } else if (EPI == 1) {
                    const float2 bb = *(const float2*)(bias + gc);
                    const float2 rr = *(const float2*)(res + (size_t)gr * N + gc);
                    *(float2*)(Cf + (size_t)gr * N + gc) =
                        make_float2(rr.x + alpha * (v0 + bb.x),
                                    rr.y + alpha * (v1 + bb.y));
                } else if (EPI == 2) {
                    const float2 bb = *(const float2*)(bias + gc);
                    *(uint32_t*)(Cb + (size_t)gr * N + gc) =
                        pk2(gelu_f(v0 + bb.x), gelu_f(v1 + bb.y));
                } else {
                    *(uint32_t*)(Cb + (size_t)gr * N + gc) = pk2(v0, v1);
                }
            }
        }
    }
}

#define GEMM_SMEM_128 (3 * (128 + 128) * 128)   //  98304
#define GEMM_SMEM_256 (3 * (128 + 256) * 128)   // 147456

// ---------------------------------------------------------------------------
// Flash attention, bf16 mma.sync, register-resident online softmax.
// Block = (b, h, 128-row q tile), 256 threads (8 warps x 16 q rows).
// KV tiles of 64, double-buffered cp.async. K/V live in fused KVB buffer
// (row stride KVW=2048; V at column offset 1024). Scores * 0.5 (1/TAU).
// SMEM: Q 16KB + 2 stages x (K 8KB + V 8KB) = 48KB.
// ---------------------------------------------------------------------------
#define AT_SMEM 49152

__global__ __launch_bounds__(256) void attn_mma(
    const __nv_bfloat16* __restrict__ Q, const __nv_bfloat16* __restrict__ KV,
    __nv_bfloat16* __restrict__ O)
{
    extern __shared__ char smc[];
    const uint32_t Qs  = smem_u32(smc);
    const uint32_t KV0 = Qs + 16384;

    const int tid = threadIdx.x, wid = tid >> 5, lane = tid & 31;
    const int qt = blockIdx.x, h = blockIdx.y, b = blockIdx.z;

    const __nv_bfloat16* Qg = Q + ((size_t)(b * NLQ + qt * 128)) * NDIM + h * NHD;
    const __nv_bfloat16* Kg = KV + ((size_t)b * NLKV) * KVW + h * NHD;
    const __nv_bfloat16* Vg = Kg + 1024;

    // Q tile: 128 rows x 128B, swizzled
    {
        const int r = tid >> 1, c0 = (tid & 1) * 4;
#pragma unroll
        for (int i = 0; i < 4; i++) {
            const int c = c0 + i;
            cp16(Qs + r * 128 + ((c ^ (r & 7)) * 16), Qg + (size_t)r * NDIM + c * 8);
        }
    }
    CP_COMMIT();
    // KV tile 0 -> stage 0
    {
        const int r = tid >> 2, c0 = (tid & 3) * 2;
#pragma unroll
        for (int i = 0; i < 2; i++) {
            const int c = c0 + i;
            const uint32_t so = r * 128 + ((c ^ (r & 7)) * 16);
            cp16(KV0 + so, Kg + (size_t)r * KVW + c * 8);
            cp16(KV0 + 8192 + so, Vg + (size_t)r * KVW + c * 8);
        }
    }
    CP_COMMIT();
    CP_WAIT1();   // Q resident
    __syncthreads();

    // Q fragments (A operand), kept for the whole KV loop
    uint32_t qa[4][4];
    const int lr = lane & 15, lh = lane >> 4;
#pragma unroll
    for (int ks = 0; ks < 4; ks++) {
        const int rr = wid * 16 + lr, ch = ks * 2 + lh;
        ldm_x4(qa[ks], Qs + rr * 128 + ((ch ^ (rr & 7)) * 16));
    }

    float oc[8][4];
#pragma unroll
    for (int dj = 0; dj < 8; dj++)
#pragma unroll
        for (int e = 0; e < 4; e++) oc[dj][e] = 0.f;
    float m0 = -1e30f, m1 = -1e30f, l0 = 0.f, l1 = 0.f;

    for (int kt = 0; kt < NLKV / 64; kt++) {
        __syncthreads();
        if (kt + 1 < NLKV / 64) {
            const uint32_t st = KV0 + ((kt + 1) & 1) * 16384;
            const int r = tid >> 2, c0 = (tid & 3) * 2;
            const __nv_bfloat16* kg = Kg + (size_t)((kt + 1) * 64 + r) * KVW;
            const __nv_bfloat16* vg = Vg + (size_t)((kt + 1) * 64 + r) * KVW;
#pragma unroll
            for (int i = 0; i < 2; i++) {
                const int c = c0 + i;
                const uint32_t so = r * 128 + ((c ^ (r & 7)) * 16);
                cp16(st + so, kg + c * 8);
                cp16(st + 8192 + so, vg + c * 8);
            }
            CP_COMMIT();
            CP_WAIT1();
        } else {
            CP_WAIT0();
        }
        __syncthreads();

        const uint32_t Kb = KV0 + (kt & 1) * 16384;
        const uint32_t Vb = Kb + 8192;

        // S = Q K^T  (warp: 16 q rows x 64 kv cols)
        float sc[8][4];
#pragma unroll
        for (int ni = 0; ni < 8; ni++)
#pragma unroll
            for (int e = 0; e < 4; e++) sc[ni][e] = 0.f;
#pragma unroll
        for (int ks = 0; ks < 4; ks++) {
            uint32_t bq[4][4];
            const int ch = ks * 2 + lh;
#pragma unroll
            for (int bi = 0; bi < 4; bi++) {
                const int rr = bi * 16 + lr;
                ldm_x4(bq[bi], Kb + rr * 128 + ((ch ^ (rr & 7)) * 16));
            }
#pragma unroll
            for (int ni = 0; ni < 8; ni++)
                mma16816(sc[ni], qa[ks], bq[ni >> 1][ni & 1], bq[ni >> 1][(ni & 1) + 2]);
        }

        // scale + register-resident online softmax
        float nm0 = -1e30f, nm1 = -1e30f;
#pragma unroll
        for (int ni = 0; ni < 8; ni++) {
            sc[ni][0] *= 0.5f; sc[ni][1] *= 0.5f; sc[ni][2] *= 0.5f; sc[ni][3] *= 0.5f;
            nm0 = fmaxf(nm0, fmaxf(sc[ni][0], sc[ni][1]));
            nm1 = fmaxf(nm1, fmaxf(sc[ni][2], sc[ni][3]));
        }
        nm0 = fmaxf(nm0, __shfl_xor_sync(0xffffffffu, nm0, 1));
        nm0 = fmaxf(nm0, __shfl_xor_sync(0xffffffffu, nm0, 2));
        nm1 = fmaxf(nm1, __shfl_xor_sync(0xffffffffu, nm1, 1));
        nm1 = fmaxf(nm1, __shfl_xor_sync(0xffffffffu, nm1, 2));
        const float mt0 = fmaxf(m0, nm0), mt1 = fmaxf(m1, nm1);
        const float c0 = __expf(m0 - mt0), c1 = __expf(m1 - mt1);
        m0 = mt0; m1 = mt1;
        float s0 = 0.f, s1 = 0.f;
#pragma unroll
        for (int ni = 0; ni < 8; ni++) {
            sc[ni][0] = __expf(sc[ni][0] - mt0);
            sc[ni][1] = __expf(sc[ni][1] - mt0);
            sc[ni][2] = __expf(sc[ni][2] - mt1);
            sc[ni][3] = __expf(sc[ni][3] - mt1);
            s0 += sc[ni][0] + sc[ni][1];
            s1 += sc[ni][2] + sc[ni][3];
        }
        s0 += __shfl_xor_sync(0xffffffffu, s0, 1);
        s0 += __shfl_xor_sync(0xffffffffu, s0, 2);
        s1 += __shfl_xor_sync(0xffffffffu, s1, 1);
        s1 += __shfl_xor_sync(0xffffffffu, s1, 2);
        l0 = l0 * c0 + s0;
        l1 = l1 * c1 + s1;
#pragma unroll
        for (int dj = 0; dj < 8; dj++) {
            oc[dj][0] *= c0; oc[dj][1] *= c0; oc[dj][2] *= c1; oc[dj][3] *= c1;
        }

        // O += P V
#pragma unroll
        for (int t = 0; t < 4; t++) {
            uint32_t pa[4];
            pa[0] = pk2(sc[2 * t][0],     sc[2 * t][1]);
            pa[1] = pk2(sc[2 * t][2],     sc[2 * t][3]);
            pa[2] = pk2(sc[2 * t + 1][0], sc[2 * t + 1][1]);
            pa[3] = pk2(sc[2 * t + 1][2], sc[2 * t + 1][3]);
            const int rr = t * 16 + (lane & 7) + ((lane >> 3) & 1) * 8;
#pragma unroll
            for (int dj2 = 0; dj2 < 4; dj2++) {
                const int cc = dj2 * 2 + lh;
                uint32_t vb[4];
                ldm_x4_t(vb, Vb + rr * 128 + ((cc ^ (rr & 7)) * 16));
                mma16816(oc[dj2 * 2],     pa, vb[0], vb[1]);
                mma16816(oc[dj2 * 2 + 1], pa, vb[2], vb[3]);
            }
        }
    }

    const float i0 = 1.f / l0, i1 = 1.f / l1;
    __nv_bfloat16* Ob = O + ((size_t)(b * NLQ + qt * 128 + wid * 16 + (lane >> 2))) * NDIM
                          + h * NHD + (lane & 3) * 2;
#pragma unroll
    for (int dj = 0; dj < 8; dj++) {
        *(uint32_t*)(Ob + dj * 8)            = pk2(oc[dj][0] * i0, oc[dj][1] * i0);
        *(uint32_t*)(Ob + 8 * NDIM + dj * 8) = pk2(oc[dj][2] * i1, oc[dj][3] * i1);
    }
}

// ---------------------------------------------------------------------------
// Launch
// ---------------------------------------------------------------------------
extern "C" void kernel_launch(void* const* d_in, const int* in_sizes, int n_in,
                              void* d_out, int out_size)
{
    (void)in_sizes; (void)n_in; (void)out_size;
    const float* q_tokens   = (const float*)d_in[0];
    const float* kv_tokens  = (const float*)d_in[1];
    const float* q_ln_w     = (const float*)d_in[2];
    const float* q_ln_b     = (const float*)d_in[3];
    const float* kv_ln_w    = (const float*)d_in[4];
    const float* kv_ln_b    = (const float*)d_in[5];
    const float* mlp_ln_w   = (const float*)d_in[6];
    const float* mlp_ln_b   = (const float*)d_in[7];
    const float* Wq         = (const float*)d_in[8];
    const float* Wk         = (const float*)d_in[9];
    const float* Wv         = (const float*)d_in[10];
    const float* Wo         = (const float*)d_in[11];
    const float* bo         = (const float*)d_in[12];
    const float* fc1_w      = (const float*)d_in[13];
    const float* fc1_b      = (const float*)d_in[14];
    const float* fc2_w      = (const float*)d_in[15];
    const float* fc2_b      = (const float*)d_in[16];
    const float* alpha_attn = (const float*)d_in[17];
    const float* alpha_mlp  = (const float*)d_in[18];
    float* out = (float*)d_out;

    void* p;
    __nv_bfloat16 *QNB, *KVNB, *QB, *KVB, *CTXB, *HNB, *H1B;
    __nv_bfloat16 *WQB, *WKVB, *WOB, *F1B, *F2B;
    float *RES;
    cudaGetSymbolAddress(&p, g_qnb);  QNB  = (__nv_bfloat16*)p;
    cudaGetSymbolAddress(&p, g_kvnb); KVNB = (__nv_bfloat16*)p;
    cudaGetSymbolAddress(&p, g_qb);   QB   = (__nv_bfloat16*)p;
    cudaGetSymbolAddress(&p, g_kvb);  KVB  = (__nv_bfloat16*)p;
    cudaGetSymbolAddress(&p, g_ctxb); CTXB = (__nv_bfloat16*)p;
    cudaGetSymbolAddress(&p, g_hnb);  HNB  = (__nv_bfloat16*)p;
    cudaGetSymbolAddress(&p, g_h1b);  H1B  = (__nv_bfloat16*)p;
    cudaGetSymbolAddress(&p, g_wqb);  WQB  = (__nv_bfloat16*)p;
    cudaGetSymbolAddress(&p, g_wkvb); WKVB = (__nv_bfloat16*)p;
    cudaGetSymbolAddress(&p, g_wob);  WOB  = (__nv_bfloat16*)p;
    cudaGetSymbolAddress(&p, g_f1b);  F1B  = (__nv_bfloat16*)p;
    cudaGetSymbolAddress(&p, g_f2b);  F2B  = (__nv_bfloat16*)p;
    cudaGetSymbolAddress(&p, g_res);  RES  = (float*)p;

    cudaFuncSetAttribute((const void*)gemm_mma<1,128>, cudaFuncAttributeMaxDynamicSharedMemorySize, GEMM_SMEM_128);
    cudaFuncSetAttribute((const void*)gemm_mma<3,128>, cudaFuncAttributeMaxDynamicSharedMemorySize, GEMM_SMEM_128);
    cudaFuncSetAttribute((const void*)gemm_mma<2,256>, cudaFuncAttributeMaxDynamicSharedMemorySize, GEMM_SMEM_256);
    cudaFuncSetAttribute((const void*)gemm_mma<3,256>, cudaFuncAttributeMaxDynamicSharedMemorySize, GEMM_SMEM_256);
    cudaFuncSetAttribute(attn_mma, cudaFuncAttributeMaxDynamicSharedMemorySize, AT_SMEM);

    // Weight fp32 -> bf16 (fused, one launch; Wk/Wv concat into WKVB)
    conv6_kernel<<<12288, 256>>>(Wq, Wk, Wv, Wo, fc1_w, fc2_w,
                                 WQB, WKVB, WOB, F1B, F2B);

    // 1) Input LayerNorms (fused q + kv)
    ln2_kernel<<<MQ + MKV, 256>>>(q_tokens, q_ln_w, q_ln_b, QNB,
                                  kv_tokens, kv_ln_w, kv_ln_b, KVNB);

    // 2) Projections: Q (BN=128), fused K|V (BN=256, N=2048)
    gemm_mma<3,128><<<dim3(NDIM/128, MQ/128),  256, GEMM_SMEM_128>>>(
        QNB, WQB, nullptr, nullptr, nullptr, nullptr, QB, MQ, NDIM, NDIM);
    gemm_mma<3,256><<<dim3(KVW/256, MKV/128), 256, GEMM_SMEM_256>>>(
        KVNB, WKVB, nullptr, nullptr, nullptr, nullptr, KVB, MKV, KVW, NDIM);

    // 3) Per-head L2 normalization of q and k (bf16 in-place)
    l2norm_bf16_kernel<<<(MQ  * NH) / 8, 256>>>(QB,  NDIM);
    l2norm_bf16_kernel<<<(MKV * NH) / 8, 256>>>(KVB, KVW);

    // 4) Attention (HMMA) -> bf16 ctx
    attn_mma<<<dim3(NLQ/128, NH, NB), 256, AT_SMEM>>>(QB, KVB, CTXB);

    // 5) Output projection + attn residual (fp32 out)
    gemm_mma<1,128><<<dim3(NDIM/128, MQ/128), 256, GEMM_SMEM_128>>>(
        CTXB, WOB, bo, q_tokens, alpha_attn, RES, nullptr, MQ, NDIM, NDIM);

    // 6) MLP
    ln_bf16_kernel<<<MQ, 256>>>(RES, mlp_ln_w, mlp_ln_b, HNB);
    gemm_mma<2,256><<<dim3(NMH/256, MQ/128), 256, GEMM_SMEM_256>>>(
        HNB, F1B, fc1_b, nullptr, nullptr, nullptr, H1B, MQ, NMH, NDIM);
    gemm_mma<1,128><<<dim3(NDIM/128, MQ/128), 256, GEMM_SMEM_128>>>(
        H1B, F2B, fc2_b, RES, alpha_mlp, out, nullptr, MQ, NDIM, NMH);
}

// round 13
// speedup vs baseline: 5.3092x; 1.0299x over previous
#include <cuda_runtime.h>
#include <cuda_bf16.h>
#include <math.h>
#include <stdint.h>

// Problem constants
#define NB   4
#define NLQ  512
#define NLKV 2048
#define NDIM 1024
#define NH   16
#define NHD  64
#define NMH  4096

#define MQ  (NB * NLQ)    // 2048
#define MKV (NB * NLKV)   // 8192
#define KVW 2048          // fused KV output width

// ---------------------------------------------------------------------------
// Scratch (device globals; no allocation allowed)
// ---------------------------------------------------------------------------
__device__ __align__(256) __nv_bfloat16 g_qnb [MQ  * NDIM];
__device__ __align__(256) __nv_bfloat16 g_kvnb[MKV * NDIM];
__device__ __align__(256) __nv_bfloat16 g_qb  [MQ  * NDIM];
__device__ __align__(256) __nv_bfloat16 g_kvb [MKV * KVW];   // [K | V] fused
__device__ __align__(256) __nv_bfloat16 g_ctxb[MQ  * NDIM];
__device__ __align__(256) __nv_bfloat16 g_hnb [MQ  * NDIM];
__device__ __align__(256) __nv_bfloat16 g_h1b [MQ  * NMH];
__device__ __align__(256) __nv_bfloat16 g_wqb [NDIM * NDIM];
__device__ __align__(256) __nv_bfloat16 g_wkvb[KVW  * NDIM];  // rows: Wk then Wv
__device__ __align__(256) __nv_bfloat16 g_wob [NDIM * NDIM];
__device__ __align__(256) __nv_bfloat16 g_f1b [NMH * NDIM];
__device__ __align__(256) __nv_bfloat16 g_f2b [NDIM * NMH];
__device__ __align__(256) float g_res[MQ * NDIM];

// ---------------------------------------------------------------------------
// PTX helpers
// ---------------------------------------------------------------------------
__device__ __forceinline__ uint32_t smem_u32(const void* p) {
    uint32_t a;
    asm("{ .reg .u64 t; cvta.to.shared.u64 t, %1; cvt.u32.u64 %0, t; }"
        : "=r"(a) : "l"(p));
    return a;
}

__device__ __forceinline__ void cp16(uint32_t dst, const void* src) {
    asm volatile("cp.async.cg.shared.global [%0], [%1], 16;" :: "r"(dst), "l"(src));
}
#define CP_COMMIT() asm volatile("cp.async.commit_group;" ::: "memory")
#define CP_WAIT1()  asm volatile("cp.async.wait_group 1;"  ::: "memory")
#define CP_WAIT0()  asm volatile("cp.async.wait_group 0;"  ::: "memory")

__device__ __forceinline__ void ldm_x4(uint32_t* r, uint32_t addr) {
    asm volatile("ldmatrix.sync.aligned.m8n8.x4.shared.b16 {%0,%1,%2,%3}, [%4];"
        : "=r"(r[0]), "=r"(r[1]), "=r"(r[2]), "=r"(r[3]) : "r"(addr));
}

__device__ __forceinline__ void ldm_x4_t(uint32_t* r, uint32_t addr) {
    asm volatile("ldmatrix.sync.aligned.m8n8.x4.trans.shared.b16 {%0,%1,%2,%3}, [%4];"
        : "=r"(r[0]), "=r"(r[1]), "=r"(r[2]), "=r"(r[3]) : "r"(addr));
}

__device__ __forceinline__ void mma16816(float* c, const uint32_t* a,
                                         uint32_t b0, uint32_t b1) {
    asm volatile(
        "mma.sync.aligned.m16n8k16.row.col.f32.bf16.bf16.f32 "
        "{%0,%1,%2,%3}, {%4,%5,%6,%7}, {%8,%9}, {%0,%1,%2,%3};"
        : "+f"(c[0]), "+f"(c[1]), "+f"(c[2]), "+f"(c[3])
        : "r"(a[0]), "r"(a[1]), "r"(a[2]), "r"(a[3]), "r"(b0), "r"(b1));
}

__device__ __forceinline__ uint32_t pk2(float a, float b) {
    return ((uint32_t)__bfloat16_as_ushort(__float2bfloat16(b)) << 16)
         |  (uint32_t)__bfloat16_as_ushort(__float2bfloat16(a));
}

__device__ __forceinline__ float gelu_f(float x) {
    return 0.5f * x * (1.0f + erff(x * 0.70710678118654752440f));
}

// ---------------------------------------------------------------------------
// Fused weight conversion: all 6 weight matrices, one launch.
// ---------------------------------------------------------------------------
__global__ __launch_bounds__(256) void conv6_kernel(
    const float* __restrict__ wq, const float* __restrict__ wk,
    const float* __restrict__ wv, const float* __restrict__ wo,
    const float* __restrict__ f1, const float* __restrict__ f2,
    __nv_bfloat16* __restrict__ dq, __nv_bfloat16* __restrict__ dkv,
    __nv_bfloat16* __restrict__ dwo, __nv_bfloat16* __restrict__ df1,
    __nv_bfloat16* __restrict__ df2)
{
    const int b = blockIdx.x;
    const float* s; __nv_bfloat16* d; int lb;
    if      (b < 1024) { s = wq; d = dq;                 lb = b; }
    else if (b < 2048) { s = wk; d = dkv;                lb = b - 1024; }
    else if (b < 3072) { s = wv; d = dkv + 1024 * NDIM;  lb = b - 2048; }
    else if (b < 4096) { s = wo; d = dwo;                lb = b - 3072; }
    else if (b < 8192) { s = f1; d = df1;                lb = b - 4096; }
    else               { s = f2; d = df2;                lb = b - 8192; }
    const int i = lb * 1024 + threadIdx.x * 4;
    const float4 v = *(const float4*)(s + i);
    *(uint2*)(d + i) = make_uint2(pk2(v.x, v.y), pk2(v.z, v.w));
}

// ---------------------------------------------------------------------------
// LayerNorm -> bf16 (dual-input fused variant + single variant)
// ---------------------------------------------------------------------------
__device__ __forceinline__ void ln_row(
    const float* __restrict__ x, const float* __restrict__ w,
    const float* __restrict__ bp, __nv_bfloat16* __restrict__ y, int row)
{
    const int tid = threadIdx.x;
    const float4 xv = *(const float4*)(x + (size_t)row * NDIM + tid * 4);
    float s  = xv.x + xv.y + xv.z + xv.w;
    float ss = fmaf(xv.x, xv.x, fmaf(xv.y, xv.y, fmaf(xv.z, xv.z, xv.w * xv.w)));

    __shared__ float rs[8], rss[8];
#pragma unroll
    for (int o = 16; o > 0; o >>= 1) {
        s  += __shfl_xor_sync(0xffffffffu, s,  o);
        ss += __shfl_xor_sync(0xffffffffu, ss, o);
    }
    if ((tid & 31) == 0) { rs[tid >> 5] = s; rss[tid >> 5] = ss; }
    __syncthreads();
    float st = 0.f, sst = 0.f;
#pragma unroll
    for (int i = 0; i < 8; i++) { st += rs[i]; sst += rss[i]; }

    const float mu  = st * (1.f / NDIM);
    const float var = sst * (1.f / NDIM) - mu * mu;
    const float inv = rsqrtf(var + 1e-6f);

    const float4 wv = *(const float4*)(w + tid * 4);
    const float4 bv = *(const float4*)(bp + tid * 4);
    float4 o;
    o.x = (xv.x - mu) * inv * wv.x + bv.x;
    o.y = (xv.y - mu) * inv * wv.y + bv.y;
    o.z = (xv.z - mu) * inv * wv.z + bv.z;
    o.w = (xv.w - mu) * inv * wv.w + bv.w;
    *(uint2*)(y + (size_t)row * NDIM + tid * 4) = make_uint2(pk2(o.x, o.y), pk2(o.z, o.w));
}

__global__ __launch_bounds__(256) void ln2_kernel(
    const float* __restrict__ qx, const float* __restrict__ qw,
    const float* __restrict__ qb, __nv_bfloat16* __restrict__ qy,
    const float* __restrict__ kx, const float* __restrict__ kw,
    const float* __restrict__ kb, __nv_bfloat16* __restrict__ ky)
{
    const int row = blockIdx.x;
    if (row < MQ) ln_row(qx, qw, qb, qy, row);
    else          ln_row(kx, kw, kb, ky, row - MQ);
}

__global__ __launch_bounds__(256) void ln_bf16_kernel(
    const float* __restrict__ x, const float* __restrict__ w,
    const float* __restrict__ bp, __nv_bfloat16* __restrict__ y)
{
    ln_row(x, w, bp, y, blockIdx.x);
}

// ---------------------------------------------------------------------------
// Per-head L2 normalize, bf16 in-place.
// ---------------------------------------------------------------------------
__global__ __launch_bounds__(256) void l2norm_bf16_kernel(
    __nv_bfloat16* __restrict__ x, int ldc)
{
    const int hr   = blockIdx.x * 8 + (threadIdx.x >> 5);
    const int lane = threadIdx.x & 31;
    const int token = hr >> 4, h = hr & 15;
    uint32_t* p = (uint32_t*)(x + (size_t)token * ldc + h * 64) + lane;
    const uint32_t u = *p;
    const float f0 = __bfloat162float(__ushort_as_bfloat16((unsigned short)(u & 0xffff)));
    const float f1 = __bfloat162float(__ushort_as_bfloat16((unsigned short)(u >> 16)));
    float ss = f0 * f0 + f1 * f1;
#pragma unroll
    for (int o = 16; o > 0; o >>= 1) ss += __shfl_xor_sync(0xffffffffu, ss, o);
    const float inv = 1.f / fmaxf(sqrtf(ss), 1e-6f);
    *p = pk2(f0 * inv, f1 * inv);
}

// ---------------------------------------------------------------------------
// mma.sync bf16 GEMM:  C[M,N] = A[M,K] @ B[N,K]^T
// BM=128, BN=128, BK=64, 3-stage cp.async pipeline, 256 threads (8 warps,
// 2x4 layout, 64x32 warp tiles), fp32 accumulators.
// __launch_bounds__(256, 2): cap at 128 regs -> 2 CTAs/SM (16 warps resident).
// EPI: 0 fp32; 1 fp32 res+alpha*(acc+bias); 2 bf16 gelu(acc+bias); 3 bf16
// ---------------------------------------------------------------------------
#define STG_BYTES (256 * 128)            // A 16KB + B 16KB
#define GEMM_SMEM (3 * STG_BYTES)        // 98304 -> 2 CTAs/SM

template<int EPI>
__global__ __launch_bounds__(256, 2) void gemm_mma(
    const __nv_bfloat16* __restrict__ A, const __nv_bfloat16* __restrict__ B,
    const float* __restrict__ bias, const float* __restrict__ res,
    const float* __restrict__ alpha_p,
    float* __restrict__ Cf, __nv_bfloat16* __restrict__ Cb,
    int M, int N, int K)
{
    extern __shared__ char dyn[];
    const uint32_t base = smem_u32(dyn);
    const int tid  = threadIdx.x;
    const int wid  = tid >> 5, lane = tid & 31;
    const int mw   = wid & 1;
    const int nw   = wid >> 1;

    const __nv_bfloat16* Ab = A + (size_t)blockIdx.y * 128 * K;
    const __nv_bfloat16* Bb = B + (size_t)blockIdx.x * 128 * K;
    const int NK = K / 64;

    const int lrow = tid >> 1;
    const int lc0  = (tid & 1) * 4;
    const int lsw  = lrow & 7;

    float acc[4][4][4];
#pragma unroll
    for (int mi = 0; mi < 4; mi++)
#pragma unroll
        for (int ni = 0; ni < 4; ni++)
#pragma unroll
            for (int e = 0; e < 4; e++) acc[mi][ni][e] = 0.f;

#pragma unroll
    for (int p = 0; p < 2; p++) {
        const uint32_t sA = base + p * STG_BYTES;
        const uint32_t sB = sA + 128 * 128;
        const __nv_bfloat16* ag = Ab + (size_t)lrow * K + p * 64 + lc0 * 8;
        const __nv_bfloat16* bg = Bb + (size_t)lrow * K + p * 64 + lc0 * 8;
#pragma unroll
        for (int i = 0; i < 4; i++) {
            const int c = lc0 + i;
            cp16(sA + lrow * 128 + ((c ^ lsw) * 16), ag + i * 8);
            cp16(sB + lrow * 128 + ((c ^ lsw) * 16), bg + i * 8);
        }
        CP_COMMIT();
    }

    for (int kc = 0; kc < NK; kc++) {
        CP_WAIT1();
        __syncthreads();
        if (kc + 2 < NK) {
            const int sp = (kc + 2) % 3;
            const uint32_t sA = base + sp * STG_BYTES;
            const uint32_t sB = sA + 128 * 128;
            const __nv_bfloat16* ag = Ab + (size_t)lrow * K + (kc + 2) * 64 + lc0 * 8;
            const __nv_bfloat16* bg = Bb + (size_t)lrow * K + (kc + 2) * 64 + lc0 * 8;
#pragma unroll
            for (int i = 0; i < 4; i++) {
                const int c = lc0 + i;
                cp16(sA + lrow * 128 + ((c ^ lsw) * 16), ag + i * 8);
                cp16(sB + lrow * 128 + ((c ^ lsw) * 16), bg + i * 8);
            }
        }
        CP_COMMIT();

        const uint32_t sA = base + (kc % 3) * STG_BYTES + (mw * 64) * 128;
        const uint32_t sB = base + (kc % 3) * STG_BYTES + 128 * 128 + (nw * 32) * 128;
        const int lr = lane & 15;
        const int lh = lane >> 4;
#pragma unroll
        for (int ks = 0; ks < 4; ks++) {
            const int ch = ks * 2 + lh;
            uint32_t a[4][4], bq[2][4];
#pragma unroll
            for (int mi = 0; mi < 4; mi++) {
                const int rr = mi * 16 + lr;
                ldm_x4(a[mi], sA + rr * 128 + ((ch ^ (rr & 7)) * 16));
            }
#pragma unroll
            for (int bi = 0; bi < 2; bi++) {
                const int rr = bi * 16 + lr;
                ldm_x4(bq[bi], sB + rr * 128 + ((ch ^ (rr & 7)) * 16));
            }
#pragma unroll
            for (int mi = 0; mi < 4; mi++)
#pragma unroll
                for (int ni = 0; ni < 4; ni++)
                    mma16816(acc[mi][ni], a[mi],
                             bq[ni >> 1][ni & 1], bq[ni >> 1][(ni & 1) + 2]);
        }
    }

    const float alpha = (EPI == 1) ? *alpha_p : 0.f;
    const int m0 = blockIdx.y * 128 + mw * 64;
    const int n0 = blockIdx.x * 128 + nw * 32;
    const int rl = lane >> 2;
    const int cl = (lane & 3) * 2;
#pragma unroll
    for (int mi = 0; mi < 4; mi++) {
#pragma unroll
        for (int e2 = 0; e2 < 2; e2++) {
            const int gr = m0 + mi * 16 + rl + e2 * 8;
#pragma unroll
            for (int ni = 0; ni < 4; ni++) {
                const int gc = n0 + ni * 8 + cl;
                float v0 = acc[mi][ni][e2 * 2];
                float v1 = acc[mi][ni][e2 * 2 + 1];
                if (EPI == 0) {
                    *(float2*)(Cf + (size_t)gr * N + gc) = make_float2(v0, v1);
                } else if (EPI == 1) {
                    const float2 bb = *(const float2*)(bias + gc);
                    const float2 rr = *(const float2*)(res + (size_t)gr * N + gc);
                    *(float2*)(Cf + (size_t)gr * N + gc) =
                        make_float2(rr.x + alpha * (v0 + bb.x),
                                    rr.y + alpha * (v1 + bb.y));
                } else if (EPI == 2) {
                    const float2 bb = *(const float2*)(bias + gc);
                    *(uint32_t*)(Cb + (size_t)gr * N + gc) =
                        pk2(gelu_f(v0 + bb.x), gelu_f(v1 + bb.y));
                } else {
                    *(uint32_t*)(Cb + (size_t)gr * N + gc) = pk2(v0, v1);
                }
            }
        }
    }
}

// ---------------------------------------------------------------------------
// Flash attention, bf16 mma.sync, register-resident online softmax.
// Block = (b, h, 128-row q tile), 256 threads (8 warps x 16 q rows).
// KV tiles of 64, double-buffered cp.async. K/V in fused KVB (stride KVW,
// V at column offset 1024). Scores * 0.5 (1/TAU).
// ---------------------------------------------------------------------------
#define AT_SMEM 49152

__global__ __launch_bounds__(256) void attn_mma(
    const __nv_bfloat16* __restrict__ Q, const __nv_bfloat16* __restrict__ KV,
    __nv_bfloat16* __restrict__ O)
{
    extern __shared__ char smc[];
    const uint32_t Qs  = smem_u32(smc);
    const uint32_t KV0 = Qs + 16384;

    const int tid = threadIdx.x, wid = tid >> 5, lane = tid & 31;
    const int qt = blockIdx.x, h = blockIdx.y, b = blockIdx.z;

    const __nv_bfloat16* Qg = Q + ((size_t)(b * NLQ + qt * 128)) * NDIM + h * NHD;
    const __nv_bfloat16* Kg = KV + ((size_t)b * NLKV) * KVW + h * NHD;
    const __nv_bfloat16* Vg = Kg + 1024;

    {
        const int r = tid >> 1, c0 = (tid & 1) * 4;
#pragma unroll
        for (int i = 0; i < 4; i++) {
            const int c = c0 + i;
            cp16(Qs + r * 128 + ((c ^ (r & 7)) * 16), Qg + (size_t)r * NDIM + c * 8);
        }
    }
    CP_COMMIT();
    {
        const int r = tid >> 2, c0 = (tid & 3) * 2;
#pragma unroll
        for (int i = 0; i < 2; i++) {
            const int c = c0 + i;
            const uint32_t so = r * 128 + ((c ^ (r & 7)) * 16);
            cp16(KV0 + so, Kg + (size_t)r * KVW + c * 8);
            cp16(KV0 + 8192 + so, Vg + (size_t)r * KVW + c * 8);
        }
    }
    CP_COMMIT();
    CP_WAIT1();
    __syncthreads();

    uint32_t qa[4][4];
    const int lr = lane & 15, lh = lane >> 4;
#pragma unroll
    for (int ks = 0; ks < 4; ks++) {
        const int rr = wid * 16 + lr, ch = ks * 2 + lh;
        ldm_x4(qa[ks], Qs + rr * 128 + ((ch ^ (rr & 7)) * 16));
    }

    float oc[8][4];
#pragma unroll
    for (int dj = 0; dj < 8; dj++)
#pragma unroll
        for (int e = 0; e < 4; e++) oc[dj][e] = 0.f;
    float m0 = -1e30f, m1 = -1e30f, l0 = 0.f, l1 = 0.f;

    for (int kt = 0; kt < NLKV / 64; kt++) {
        __syncthreads();
        if (kt + 1 < NLKV / 64) {
            const uint32_t st = KV0 + ((kt + 1) & 1) * 16384;
            const int r = tid >> 2, c0 = (tid & 3) * 2;
            const __nv_bfloat16* kg = Kg + (size_t)((kt + 1) * 64 + r) * KVW;
            const __nv_bfloat16* vg = Vg + (size_t)((kt + 1) * 64 + r) * KVW;
#pragma unroll
            for (int i = 0; i < 2; i++) {
                const int c = c0 + i;
                const uint32_t so = r * 128 + ((c ^ (r & 7)) * 16);
                cp16(st + so, kg + c * 8);
                cp16(st + 8192 + so, vg + c * 8);
            }
            CP_COMMIT();
            CP_WAIT1();
        } else {
            CP_WAIT0();
        }
        __syncthreads();

        const uint32_t Kb = KV0 + (kt & 1) * 16384;
        const uint32_t Vb = Kb + 8192;

        float sc[8][4];
#pragma unroll
        for (int ni = 0; ni < 8; ni++)
#pragma unroll
            for (int e = 0; e < 4; e++) sc[ni][e] = 0.f;
#pragma unroll
        for (int ks = 0; ks < 4; ks++) {
            uint32_t bq[4][4];
            const int ch = ks * 2 + lh;
#pragma unroll
            for (int bi = 0; bi < 4; bi++) {
                const int rr = bi * 16 + lr;
                ldm_x4(bq[bi], Kb + rr * 128 + ((ch ^ (rr & 7)) * 16));
            }
#pragma unroll
            for (int ni = 0; ni < 8; ni++)
                mma16816(sc[ni], qa[ks], bq[ni >> 1][ni & 1], bq[ni >> 1][(ni & 1) + 2]);
        }

        float nm0 = -1e30f, nm1 = -1e30f;
#pragma unroll
        for (int ni = 0; ni < 8; ni++) {
            sc[ni][0] *= 0.5f; sc[ni][1] *= 0.5f; sc[ni][2] *= 0.5f; sc[ni][3] *= 0.5f;
            nm0 = fmaxf(nm0, fmaxf(sc[ni][0], sc[ni][1]));
            nm1 = fmaxf(nm1, fmaxf(sc[ni][2], sc[ni][3]));
        }
        nm0 = fmaxf(nm0, __shfl_xor_sync(0xffffffffu, nm0, 1));
        nm0 = fmaxf(nm0, __shfl_xor_sync(0xffffffffu, nm0, 2));
        nm1 = fmaxf(nm1, __shfl_xor_sync(0xffffffffu, nm1, 1));
        nm1 = fmaxf(nm1, __shfl_xor_sync(0xffffffffu, nm1, 2));
        const float mt0 = fmaxf(m0, nm0), mt1 = fmaxf(m1, nm1);
        const float c0 = __expf(m0 - mt0), c1 = __expf(m1 - mt1);
        m0 = mt0; m1 = mt1;
        float s0 = 0.f, s1 = 0.f;
#pragma unroll
        for (int ni = 0; ni < 8; ni++) {
            sc[ni][0] = __expf(sc[ni][0] - mt0);
            sc[ni][1] = __expf(sc[ni][1] - mt0);
            sc[ni][2] = __expf(sc[ni][2] - mt1);
            sc[ni][3] = __expf(sc[ni][3] - mt1);
            s0 += sc[ni][0] + sc[ni][1];
            s1 += sc[ni][2] + sc[ni][3];
        }
        s0 += __shfl_xor_sync(0xffffffffu, s0, 1);
        s0 += __shfl_xor_sync(0xffffffffu, s0, 2);
        s1 += __shfl_xor_sync(0xffffffffu, s1, 1);
        s1 += __shfl_xor_sync(0xffffffffu, s1, 2);
        l0 = l0 * c0 + s0;
        l1 = l1 * c1 + s1;
#pragma unroll
        for (int dj = 0; dj < 8; dj++) {
            oc[dj][0] *= c0; oc[dj][1] *= c0; oc[dj][2] *= c1; oc[dj][3] *= c1;
        }

#pragma unroll
        for (int t = 0; t < 4; t++) {
            uint32_t pa[4];
            pa[0] = pk2(sc[2 * t][0],     sc[2 * t][1]);
            pa[1] = pk2(sc[2 * t][2],     sc[2 * t][3]);
            pa[2] = pk2(sc[2 * t + 1][0], sc[2 * t + 1][1]);
            pa[3] = pk2(sc[2 * t + 1][2], sc[2 * t + 1][3]);
            const int rr = t * 16 + (lane & 7) + ((lane >> 3) & 1) * 8;
#pragma unroll
            for (int dj2 = 0; dj2 < 4; dj2++) {
                const int cc = dj2 * 2 + lh;
                uint32_t vb[4];
                ldm_x4_t(vb, Vb + rr * 128 + ((cc ^ (rr & 7)) * 16));
                mma16816(oc[dj2 * 2],     pa, vb[0], vb[1]);
                mma16816(oc[dj2 * 2 + 1], pa, vb[2], vb[3]);
            }
        }
    }

    const float i0 = 1.f / l0, i1 = 1.f / l1;
    __nv_bfloat16* Ob = O + ((size_t)(b * NLQ + qt * 128 + wid * 16 + (lane >> 2))) * NDIM
                          + h * NHD + (lane & 3) * 2;
#pragma unroll
    for (int dj = 0; dj < 8; dj++) {
        *(uint32_t*)(Ob + dj * 8)            = pk2(oc[dj][0] * i0, oc[dj][1] * i0);
        *(uint32_t*)(Ob + 8 * NDIM + dj * 8) = pk2(oc[dj][2] * i1, oc[dj][3] * i1);
    }
}

// ---------------------------------------------------------------------------
// Launch
// ---------------------------------------------------------------------------
extern "C" void kernel_launch(void* const* d_in, const int* in_sizes, int n_in,
                              void* d_out, int out_size)
{
    (void)in_sizes; (void)n_in; (void)out_size;
    const float* q_tokens   = (const float*)d_in[0];
    const float* kv_tokens  = (const float*)d_in[1];
    const float* q_ln_w     = (const float*)d_in[2];
    const float* q_ln_b     = (const float*)d_in[3];
    const float* kv_ln_w    = (const float*)d_in[4];
    const float* kv_ln_b    = (const float*)d_in[5];
    const float* mlp_ln_w   = (const float*)d_in[6];
    const float* mlp_ln_b   = (const float*)d_in[7];
    const float* Wq         = (const float*)d_in[8];
    const float* Wk         = (const float*)d_in[9];
    const float* Wv         = (const float*)d_in[10];
    const float* Wo         = (const float*)d_in[11];
    const float* bo         = (const float*)d_in[12];
    const float* fc1_w      = (const float*)d_in[13];
    const float* fc1_b      = (const float*)d_in[14];
    const float* fc2_w      = (const float*)d_in[15];
    const float* fc2_b      = (const float*)d_in[16];
    const float* alpha_attn = (const float*)d_in[17];
    const float* alpha_mlp  = (const float*)d_in[18];
    float* out = (float*)d_out;

    void* p;
    __nv_bfloat16 *QNB, *KVNB, *QB, *KVB, *CTXB, *HNB, *H1B;
    __nv_bfloat16 *WQB, *WKVB, *WOB, *F1B, *F2B;
    float *RES;
    cudaGetSymbolAddress(&p, g_qnb);  QNB  = (__nv_bfloat16*)p;
    cudaGetSymbolAddress(&p, g_kvnb); KVNB = (__nv_bfloat16*)p;
    cudaGetSymbolAddress(&p, g_qb);   QB   = (__nv_bfloat16*)p;
    cudaGetSymbolAddress(&p, g_kvb);  KVB  = (__nv_bfloat16*)p;
    cudaGetSymbolAddress(&p, g_ctxb); CTXB = (__nv_bfloat16*)p;
    cudaGetSymbolAddress(&p, g_hnb);  HNB  = (__nv_bfloat16*)p;
    cudaGetSymbolAddress(&p, g_h1b);  H1B  = (__nv_bfloat16*)p;
    cudaGetSymbolAddress(&p, g_wqb);  WQB  = (__nv_bfloat16*)p;
    cudaGetSymbolAddress(&p, g_wkvb); WKVB = (__nv_bfloat16*)p;
    cudaGetSymbolAddress(&p, g_wob);  WOB  = (__nv_bfloat16*)p;
    cudaGetSymbolAddress(&p, g_f1b);  F1B  = (__nv_bfloat16*)p;
    cudaGetSymbolAddress(&p, g_f2b);  F2B  = (__nv_bfloat16*)p;
    cudaGetSymbolAddress(&p, g_res);  RES  = (float*)p;

    cudaFuncSetAttribute((const void*)gemm_mma<1>, cudaFuncAttributeMaxDynamicSharedMemorySize, GEMM_SMEM);
    cudaFuncSetAttribute((const void*)gemm_mma<2>, cudaFuncAttributeMaxDynamicSharedMemorySize, GEMM_SMEM);
    cudaFuncSetAttribute((const void*)gemm_mma<3>, cudaFuncAttributeMaxDynamicSharedMemorySize, GEMM_SMEM);
    cudaFuncSetAttribute(attn_mma, cudaFuncAttributeMaxDynamicSharedMemorySize, AT_SMEM);

    // Weight fp32 -> bf16 (fused; Wk/Wv concat into WKVB)
    conv6_kernel<<<12288, 256>>>(Wq, Wk, Wv, Wo, fc1_w, fc2_w,
                                 WQB, WKVB, WOB, F1B, F2B);

    // 1) Input LayerNorms (fused q + kv)
    ln2_kernel<<<MQ + MKV, 256>>>(q_tokens, q_ln_w, q_ln_b, QNB,
                                  kv_tokens, kv_ln_w, kv_ln_b, KVNB);

    // 2) Projections: Q and fused K|V (N = 2048)
    gemm_mma<3><<<dim3(NDIM/128, MQ/128),  256, GEMM_SMEM>>>(
        QNB, WQB, nullptr, nullptr, nullptr, nullptr, QB, MQ, NDIM, NDIM);
    gemm_mma<3><<<dim3(KVW/128, MKV/128), 256, GEMM_SMEM>>>(
        KVNB, WKVB, nullptr, nullptr, nullptr, nullptr, KVB, MKV, KVW, NDIM);

    // 3) Per-head L2 normalization of q and k (bf16 in-place)
    l2norm_bf16_kernel<<<(MQ  * NH) / 8, 256>>>(QB,  NDIM);
    l2norm_bf16_kernel<<<(MKV * NH) / 8, 256>>>(KVB, KVW);

    // 4) Attention (HMMA) -> bf16 ctx
    attn_mma<<<dim3(NLQ/128, NH, NB), 256, AT_SMEM>>>(QB, KVB, CTXB);

    // 5) Output projection + attn residual (fp32 out)
    gemm_mma<1><<<dim3(NDIM/128, MQ/128), 256, GEMM_SMEM>>>(
        CTXB, WOB, bo, q_tokens, alpha_attn, RES, nullptr, MQ, NDIM, NDIM);

    // 6) MLP
    ln_bf16_kernel<<<MQ, 256>>>(RES, mlp_ln_w, mlp_ln_b, HNB);
    gemm_mma<2><<<dim3(NMH/128, MQ/128), 256, GEMM_SMEM>>>(
        HNB, F1B, fc1_b, nullptr, nullptr, nullptr, H1B, MQ, NMH, NDIM);
    gemm_mma<1><<<dim3(NDIM/128, MQ/128), 256, GEMM_SMEM>>>(
        H1B, F2B, fc2_b, RES, alpha_mlp, out, nullptr, MQ, NDIM, NMH);
}

// round 17
// speedup vs baseline: 5.8260x; 1.0973x over previous
#include <cuda_runtime.h>
#include <cuda_bf16.h>
#include <cuda_fp8.h>
#include <math.h>
#include <stdint.h>

// Problem constants
#define NB   4
#define NLQ  512
#define NLKV 2048
#define NDIM 1024
#define NH   16
#define NHD  64
#define NMH  4096

#define MQ  (NB * NLQ)    // 2048
#define MKV (NB * NLKV)   // 8192
#define KVW 2048          // fused KV output width

// ---------------------------------------------------------------------------
// Scratch (device globals; no allocation allowed)
// ---------------------------------------------------------------------------
__device__ __align__(256) uint8_t g_qnb [MQ  * NDIM];          // fp8 ln(q)
__device__ __align__(256) uint8_t g_kvnb[MKV * NDIM];          // fp8 ln(kv)
__device__ __align__(256) __nv_bfloat16 g_qb  [MQ  * NDIM];    // bf16 q
__device__ __align__(256) __nv_bfloat16 g_kvb [MKV * KVW];     // bf16 [K|V]
__device__ __align__(256) uint8_t g_ctxb[MQ  * NDIM];          // fp8 ctx*16
__device__ __align__(256) uint8_t g_hnb [MQ  * NDIM];          // fp8 ln(res)
__device__ __align__(256) uint8_t g_h1b [MQ  * NMH];           // fp8 gelu out
__device__ __align__(256) uint8_t g_wqb [NDIM * NDIM];         // fp8 weights
__device__ __align__(256) uint8_t g_wkvb[KVW  * NDIM];
__device__ __align__(256) uint8_t g_wob [NDIM * NDIM];
__device__ __align__(256) uint8_t g_f1b [NMH * NDIM];
__device__ __align__(256) uint8_t g_f2b [NDIM * NMH];
__device__ __align__(256) float g_res[MQ * NDIM];

// ---------------------------------------------------------------------------
// PTX helpers
// ---------------------------------------------------------------------------
__device__ __forceinline__ uint32_t smem_u32(const void* p) {
    uint32_t a;
    asm("{ .reg .u64 t; cvta.to.shared.u64 t, %1; cvt.u32.u64 %0, t; }"
        : "=r"(a) : "l"(p));
    return a;
}

__device__ __forceinline__ void cp16(uint32_t dst, const void* src) {
    asm volatile("cp.async.cg.shared.global [%0], [%1], 16;" :: "r"(dst), "l"(src));
}
#define CP_COMMIT() asm volatile("cp.async.commit_group;" ::: "memory")
#define CP_WAIT1()  asm volatile("cp.async.wait_group 1;"  ::: "memory")
#define CP_WAIT0()  asm volatile("cp.async.wait_group 0;"  ::: "memory")

__device__ __forceinline__ void ldm_x4(uint32_t* r, uint32_t addr) {
    asm volatile("ldmatrix.sync.aligned.m8n8.x4.shared.b16 {%0,%1,%2,%3}, [%4];"
        : "=r"(r[0]), "=r"(r[1]), "=r"(r[2]), "=r"(r[3]) : "r"(addr));
}

__device__ __forceinline__ void ldm_x4_t(uint32_t* r, uint32_t addr) {
    asm volatile("ldmatrix.sync.aligned.m8n8.x4.trans.shared.b16 {%0,%1,%2,%3}, [%4];"
        : "=r"(r[0]), "=r"(r[1]), "=r"(r[2]), "=r"(r[3]) : "r"(addr));
}

// bf16 m16n8k16 (attention)
__device__ __forceinline__ void mma16816(float* c, const uint32_t* a,
                                         uint32_t b0, uint32_t b1) {
    asm volatile(
        "mma.sync.aligned.m16n8k16.row.col.f32.bf16.bf16.f32 "
        "{%0,%1,%2,%3}, {%4,%5,%6,%7}, {%8,%9}, {%0,%1,%2,%3};"
        : "+f"(c[0]), "+f"(c[1]), "+f"(c[2]), "+f"(c[3])
        : "r"(a[0]), "r"(a[1]), "r"(a[2]), "r"(a[3]), "r"(b0), "r"(b1));
}

// fp8 e4m3 m16n8k32 (GEMMs) — same register shape as bf16 16816
__device__ __forceinline__ void mma16832f8(float* c, const uint32_t* a,
                                           uint32_t b0, uint32_t b1) {
    asm volatile(
        "mma.sync.aligned.m16n8k32.row.col.f32.e4m3.e4m3.f32 "
        "{%0,%1,%2,%3}, {%4,%5,%6,%7}, {%8,%9}, {%0,%1,%2,%3};"
        : "+f"(c[0]), "+f"(c[1]), "+f"(c[2]), "+f"(c[3])
        : "r"(a[0]), "r"(a[1]), "r"(a[2]), "r"(a[3]), "r"(b0), "r"(b1));
}

__device__ __forceinline__ uint32_t pk2(float a, float b) {
    return ((uint32_t)__bfloat16_as_ushort(__float2bfloat16(b)) << 16)
         |  (uint32_t)__bfloat16_as_ushort(__float2bfloat16(a));
}

__device__ __forceinline__ unsigned short f8x2(float a, float b) {
    return (unsigned short)__nv_cvt_float2_to_fp8x2(make_float2(a, b),
                                                    __NV_SATFINITE, __NV_E4M3);
}

__device__ __forceinline__ uint32_t pk4f8(float a, float b, float c, float d) {
    return (uint32_t)f8x2(a, b) | ((uint32_t)f8x2(c, d) << 16);
}

__device__ __forceinline__ float gelu_f(float x) {
    return 0.5f * x * (1.0f + erff(x * 0.70710678118654752440f));
}

// ---------------------------------------------------------------------------
// Fused weight conversion fp32 -> fp8 (all 6 matrices, one launch).
// ---------------------------------------------------------------------------
__global__ __launch_bounds__(256) void conv6_kernel(
    const float* __restrict__ wq, const float* __restrict__ wk,
    const float* __restrict__ wv, const float* __restrict__ wo,
    const float* __restrict__ f1, const float* __restrict__ f2,
    uint8_t* __restrict__ dq, uint8_t* __restrict__ dkv,
    uint8_t* __restrict__ dwo, uint8_t* __restrict__ df1,
    uint8_t* __restrict__ df2)
{
    const int b = blockIdx.x;
    const float* s; uint8_t* d; int lb;
    if      (b < 1024) { s = wq; d = dq;                 lb = b; }
    else if (b < 2048) { s = wk; d = dkv;                lb = b - 1024; }
    else if (b < 3072) { s = wv; d = dkv + 1024 * NDIM;  lb = b - 2048; }
    else if (b < 4096) { s = wo; d = dwo;                lb = b - 3072; }
    else if (b < 8192) { s = f1; d = df1;                lb = b - 4096; }
    else               { s = f2; d = df2;                lb = b - 8192; }
    const int i = lb * 1024 + threadIdx.x * 4;
    const float4 v = *(const float4*)(s + i);
    *(uint32_t*)(d + i) = pk4f8(v.x, v.y, v.z, v.w);
}

// ---------------------------------------------------------------------------
// LayerNorm -> fp8 output. One block per row of 1024.
// ---------------------------------------------------------------------------
__device__ __forceinline__ void ln_row(
    const float* __restrict__ x, const float* __restrict__ w,
    const float* __restrict__ bp, uint8_t* __restrict__ y, int row)
{
    const int tid = threadIdx.x;
    const float4 xv = *(const float4*)(x + (size_t)row * NDIM + tid * 4);
    float s  = xv.x + xv.y + xv.z + xv.w;
    float ss = fmaf(xv.x, xv.x, fmaf(xv.y, xv.y, fmaf(xv.z, xv.z, xv.w * xv.w)));

    __shared__ float rs[8], rss[8];
#pragma unroll
    for (int o = 16; o > 0; o >>= 1) {
        s  += __shfl_xor_sync(0xffffffffu, s,  o);
        ss += __shfl_xor_sync(0xffffffffu, ss, o);
    }
    if ((tid & 31) == 0) { rs[tid >> 5] = s; rss[tid >> 5] = ss; }
    __syncthreads();
    float st = 0.f, sst = 0.f;
#pragma unroll
    for (int i = 0; i < 8; i++) { st += rs[i]; sst += rss[i]; }

    const float mu  = st * (1.f / NDIM);
    const float var = sst * (1.f / NDIM) - mu * mu;
    const float inv = rsqrtf(var + 1e-6f);

    const float4 wv = *(const float4*)(w + tid * 4);
    const float4 bv = *(const float4*)(bp + tid * 4);
    float4 o;
    o.x = (xv.x - mu) * inv * wv.x + bv.x;
    o.y = (xv.y - mu) * inv * wv.y + bv.y;
    o.z = (xv.z - mu) * inv * wv.z + bv.z;
    o.w = (xv.w - mu) * inv * wv.w + bv.w;
    *(uint32_t*)(y + (size_t)row * NDIM + tid * 4) = pk4f8(o.x, o.y, o.z, o.w);
}

__global__ __launch_bounds__(256) void ln2_kernel(
    const float* __restrict__ qx, const float* __restrict__ qw,
    const float* __restrict__ qb, uint8_t* __restrict__ qy,
    const float* __restrict__ kx, const float* __restrict__ kw,
    const float* __restrict__ kb, uint8_t* __restrict__ ky)
{
    const int row = blockIdx.x;
    if (row < MQ) ln_row(qx, qw, qb, qy, row);
    else          ln_row(kx, kw, kb, ky, row - MQ);
}

__global__ __launch_bounds__(256) void ln_f8_kernel(
    const float* __restrict__ x, const float* __restrict__ w,
    const float* __restrict__ bp, uint8_t* __restrict__ y)
{
    ln_row(x, w, bp, y, blockIdx.x);
}

// ---------------------------------------------------------------------------
// Per-head L2 normalize, bf16 in-place.
// ---------------------------------------------------------------------------
__global__ __launch_bounds__(256) void l2norm_bf16_kernel(
    __nv_bfloat16* __restrict__ x, int ldc)
{
    const int hr   = blockIdx.x * 8 + (threadIdx.x >> 5);
    const int lane = threadIdx.x & 31;
    const int token = hr >> 4, h = hr & 15;
    uint32_t* p = (uint32_t*)(x + (size_t)token * ldc + h * 64) + lane;
    const uint32_t u = *p;
    const float f0 = __bfloat162float(__ushort_as_bfloat16((unsigned short)(u & 0xffff)));
    const float f1 = __bfloat162float(__ushort_as_bfloat16((unsigned short)(u >> 16)));
    float ss = f0 * f0 + f1 * f1;
#pragma unroll
    for (int o = 16; o > 0; o >>= 1) ss += __shfl_xor_sync(0xffffffffu, ss, o);
    const float inv = 1.f / fmaxf(sqrtf(ss), 1e-6f);
    *p = pk2(f0 * inv, f1 * inv);
}

// ---------------------------------------------------------------------------
// FP8 e4m3 mma.sync GEMM:  C[M,N] = A[M,K] @ B[N,K]^T  (A, B e4m3, K-contig)
// BM=128, BN=128, BK=128 (bytes = elements), 3-stage cp.async pipeline,
// 256 threads (8 warps, 2x4, 64x32 warp tiles), fp32 accumulators.
// Same 128B-row XOR-swizzled SMEM layout as the bf16 version; fragment
// chunk pairs (k-lo/k-hi 16B) map identically to e4m3 m16n8k32 fragments.
// EPI: 1 fp32 res + alpha*ascale*(acc+bias); 2 fp8 gelu(acc+bias); 3 bf16
// ---------------------------------------------------------------------------
#define STG_BYTES (256 * 128)            // A 16KB + B 16KB
#define GEMM_SMEM (3 * STG_BYTES)        // 98304 -> 2 CTAs/SM

template<int EPI>
__global__ __launch_bounds__(256, 2) void gemm_mma(
    const uint8_t* __restrict__ A, const uint8_t* __restrict__ B,
    const float* __restrict__ bias, const float* __restrict__ res,
    const float* __restrict__ alpha_p, float ascale,
    float* __restrict__ Cf, __nv_bfloat16* __restrict__ Cb,
    uint8_t* __restrict__ C8,
    int M, int N, int K)
{
    extern __shared__ char dyn[];
    const uint32_t base = smem_u32(dyn);
    const int tid  = threadIdx.x;
    const int wid  = tid >> 5, lane = tid & 31;
    const int mw   = wid & 1;
    const int nw   = wid >> 1;

    const uint8_t* Ab = A + (size_t)blockIdx.y * 128 * K;
    const uint8_t* Bb = B + (size_t)blockIdx.x * 128 * K;
    const int NK = K / 128;

    const int lrow = tid >> 1;
    const int lc0  = (tid & 1) * 4;
    const int lsw  = lrow & 7;

    float acc[4][4][4];
#pragma unroll
    for (int mi = 0; mi < 4; mi++)
#pragma unroll
        for (int ni = 0; ni < 4; ni++)
#pragma unroll
            for (int e = 0; e < 4; e++) acc[mi][ni][e] = 0.f;

#pragma unroll
    for (int p = 0; p < 2; p++) {
        const uint32_t sA = base + p * STG_BYTES;
        const uint32_t sB = sA + 128 * 128;
        const uint8_t* ag = Ab + (size_t)lrow * K + p * 128 + lc0 * 16;
        const uint8_t* bg = Bb + (size_t)lrow * K + p * 128 + lc0 * 16;
#pragma unroll
        for (int i = 0; i < 4; i++) {
            const int c = lc0 + i;
            cp16(sA + lrow * 128 + ((c ^ lsw) * 16), ag + i * 16);
            cp16(sB + lrow * 128 + ((c ^ lsw) * 16), bg + i * 16);
        }
        CP_COMMIT();
    }

    for (int kc = 0; kc < NK; kc++) {
        CP_WAIT1();
        __syncthreads();
        if (kc + 2 < NK) {
            const int sp = (kc + 2) % 3;
            const uint32_t sA = base + sp * STG_BYTES;
            const uint32_t sB = sA + 128 * 128;
            const uint8_t* ag = Ab + (size_t)lrow * K + (kc + 2) * 128 + lc0 * 16;
            const uint8_t* bg = Bb + (size_t)lrow * K + (kc + 2) * 128 + lc0 * 16;
#pragma unroll
            for (int i = 0; i < 4; i++) {
                const int c = lc0 + i;
                cp16(sA + lrow * 128 + ((c ^ lsw) * 16), ag + i * 16);
                cp16(sB + lrow * 128 + ((c ^ lsw) * 16), bg + i * 16);
            }
        }
        CP_COMMIT();

        const uint32_t sA = base + (kc % 3) * STG_BYTES + (mw * 64) * 128;
        const uint32_t sB = base + (kc % 3) * STG_BYTES + 128 * 128 + (nw * 32) * 128;
        const int lr = lane & 15;
        const int lh = lane >> 4;
#pragma unroll
        for (int ks = 0; ks < 4; ks++) {      // each ks = k32 e4m3 = 32B
            const int ch = ks * 2 + lh;       // 16B chunk pair (k-lo / k-hi)
            uint32_t a[4][4], bq[2][4];
#pragma unroll
            for (int mi = 0; mi < 4; mi++) {
                const int rr = mi * 16 + lr;
                ldm_x4(a[mi], sA + rr * 128 + ((ch ^ (rr & 7)) * 16));
            }
#pragma unroll
            for (int bi = 0; bi < 2; bi++) {
                const int rr = bi * 16 + lr;
                ldm_x4(bq[bi], sB + rr * 128 + ((ch ^ (rr & 7)) * 16));
            }
#pragma unroll
            for (int mi = 0; mi < 4; mi++)
#pragma unroll
                for (int ni = 0; ni < 4; ni++)
                    mma16832f8(acc[mi][ni], a[mi],
                               bq[ni >> 1][ni & 1], bq[ni >> 1][(ni & 1) + 2]);
        }
    }

    const float alpha = (EPI == 1) ? (*alpha_p) * ascale : 0.f;
    const int m0 = blockIdx.y * 128 + mw * 64;
    const int n0 = blockIdx.x * 128 + nw * 32;
    const int rl = lane >> 2;
    const int cl = (lane & 3) * 2;
#pragma unroll
    for (int mi = 0; mi < 4; mi++) {
#pragma unroll
        for (int e2 = 0; e2 < 2; e2++) {
            const int gr = m0 + mi * 16 + rl + e2 * 8;
#pragma unroll
            for (int ni = 0; ni < 4; ni++) {
                const int gc = n0 + ni * 8 + cl;
                float v0 = acc[mi][ni][e2 * 2];
                float v1 = acc[mi][ni][e2 * 2 + 1];
                if (EPI == 1) {
                    const float2 bb = *(const float2*)(bias + gc);
                    const float2 rr = *(const float2*)(res + (size_t)gr * N + gc);
                    *(float2*)(Cf + (size_t)gr * N + gc) =
                        make_float2(rr.x + alpha * (v0 + bb.x),
                                    rr.y + alpha * (v1 + bb.y));
                } else if (EPI == 2) {
                    const float2 bb = *(const float2*)(bias + gc);
                    *(unsigned short*)(C8 + (size_t)gr * N + gc) =
                        f8x2(gelu_f(v0 + bb.x), gelu_f(v1 + bb.y));
                } else {
                    *(uint32_t*)(Cb + (size_t)gr * N + gc) = pk2(v0, v1);
                }
            }
        }
    }
}

// ---------------------------------------------------------------------------
// Flash attention, bf16 mma.sync, register-resident online softmax.
// Block = (b, h, 128-row q tile), 256 threads (8 warps x 16 q rows).
// KV tiles of 64, double-buffered cp.async. K/V in fused KVB (stride KVW,
// V at column offset 1024). Scores * 0.5 (1/TAU). Output fp8 ctx * 16.
// ---------------------------------------------------------------------------
#define AT_SMEM 49152

__global__ __launch_bounds__(256) void attn_mma(
    const __nv_bfloat16* __restrict__ Q, const __nv_bfloat16* __restrict__ KV,
    uint8_t* __restrict__ O)
{
    extern __shared__ char smc[];
    const uint32_t Qs  = smem_u32(smc);
    const uint32_t KV0 = Qs + 16384;

    const int tid = threadIdx.x, wid = tid >> 5, lane = tid & 31;
    const int qt = blockIdx.x, h = blockIdx.y, b = blockIdx.z;

    const __nv_bfloat16* Qg = Q + ((size_t)(b * NLQ + qt * 128)) * NDIM + h * NHD;
    const __nv_bfloat16* Kg = KV + ((size_t)b * NLKV) * KVW + h * NHD;
    const __nv_bfloat16* Vg = Kg + 1024;

    {
        const int r = tid >> 1, c0 = (tid & 1) * 4;
#pragma unroll
        for (int i = 0; i < 4; i++) {
            const int c = c0 + i;
            cp16(Qs + r * 128 + ((c ^ (r & 7)) * 16), Qg + (size_t)r * NDIM + c * 8);
        }
    }
    CP_COMMIT();
    {
        const int r = tid >> 2, c0 = (tid & 3) * 2;
#pragma unroll
        for (int i = 0; i < 2; i++) {
            const int c = c0 + i;
            const uint32_t so = r * 128 + ((c ^ (r & 7)) * 16);
            cp16(KV0 + so, Kg + (size_t)r * KVW + c * 8);
            cp16(KV0 + 8192 + so, Vg + (size_t)r * KVW + c * 8);
        }
    }
    CP_COMMIT();
    CP_WAIT1();
    __syncthreads();

    uint32_t qa[4][4];
    const int lr = lane & 15, lh = lane >> 4;
#pragma unroll
    for (int ks = 0; ks < 4; ks++) {
        const int rr = wid * 16 + lr, ch = ks * 2 + lh;
        ldm_x4(qa[ks], Qs + rr * 128 + ((ch ^ (rr & 7)) * 16));
    }

    float oc[8][4];
#pragma unroll
    for (int dj = 0; dj < 8; dj++)
#pragma unroll
        for (int e = 0; e < 4; e++) oc[dj][e] = 0.f;
    float m0 = -1e30f, m1 = -1e30f, l0 = 0.f, l1 = 0.f;

    for (int kt = 0; kt < NLKV / 64; kt++) {
        __syncthreads();
        if (kt + 1 < NLKV / 64) {
            const uint32_t st = KV0 + ((kt + 1) & 1) * 16384;
            const int r = tid >> 2, c0 = (tid & 3) * 2;
            const __nv_bfloat16* kg = Kg + (size_t)((kt + 1) * 64 + r) * KVW;
            const __nv_bfloat16* vg = Vg + (size_t)((kt + 1) * 64 + r) * KVW;
#pragma unroll
            for (int i = 0; i < 2; i++) {
                const int c = c0 + i;
                const uint32_t so = r * 128 + ((c ^ (r & 7)) * 16);
                cp16(st + so, kg + c * 8);
                cp16(st + 8192 + so, vg + c * 8);
            }
            CP_COMMIT();
            CP_WAIT1();
        } else {
            CP_WAIT0();
        }
        __syncthreads();

        const uint32_t Kb = KV0 + (kt & 1) * 16384;
        const uint32_t Vb = Kb + 8192;

        float sc[8][4];
#pragma unroll
        for (int ni = 0; ni < 8; ni++)
#pragma unroll
            for (int e = 0; e < 4; e++) sc[ni][e] = 0.f;
#pragma unroll
        for (int ks = 0; ks < 4; ks++) {
            uint32_t bq[4][4];
            const int ch = ks * 2 + lh;
#pragma unroll
            for (int bi = 0; bi < 4; bi++) {
                const int rr = bi * 16 + lr;
                ldm_x4(bq[bi], Kb + rr * 128 + ((ch ^ (rr & 7)) * 16));
            }
#pragma unroll
            for (int ni = 0; ni < 8; ni++)
                mma16816(sc[ni], qa[ks], bq[ni >> 1][ni & 1], bq[ni >> 1][(ni & 1) + 2]);
        }

        float nm0 = -1e30f, nm1 = -1e30f;
#pragma unroll
        for (int ni = 0; ni < 8; ni++) {
            sc[ni][0] *= 0.5f; sc[ni][1] *= 0.5f; sc[ni][2] *= 0.5f; sc[ni][3] *= 0.5f;
            nm0 = fmaxf(nm0, fmaxf(sc[ni][0], sc[ni][1]));
            nm1 = fmaxf(nm1, fmaxf(sc[ni][2], sc[ni][3]));
        }
        nm0 = fmaxf(nm0, __shfl_xor_sync(0xffffffffu, nm0, 1));
        nm0 = fmaxf(nm0, __shfl_xor_sync(0xffffffffu, nm0, 2));
        nm1 = fmaxf(nm1, __shfl_xor_sync(0xffffffffu, nm1, 1));
        nm1 = fmaxf(nm1, __shfl_xor_sync(0xffffffffu, nm1, 2));
        const float mt0 = fmaxf(m0, nm0), mt1 = fmaxf(m1, nm1);
        const float c0 = __expf(m0 - mt0), c1 = __expf(m1 - mt1);
        m0 = mt0; m1 = mt1;
        float s0 = 0.f, s1 = 0.f;
#pragma unroll
        for (int ni = 0; ni < 8; ni++) {
            sc[ni][0] = __expf(sc[ni][0] - mt0);
            sc[ni][1] = __expf(sc[ni][1] - mt0);
            sc[ni][2] = __expf(sc[ni][2] - mt1);
            sc[ni][3] = __expf(sc[ni][3] - mt1);
            s0 += sc[ni][0] + sc[ni][1];
            s1 += sc[ni][2] + sc[ni][3];
        }
        s0 += __shfl_xor_sync(0xffffffffu, s0, 1);
        s0 += __shfl_xor_sync(0xffffffffu, s0, 2);
        s1 += __shfl_xor_sync(0xffffffffu, s1, 1);
        s1 += __shfl_xor_sync(0xffffffffu, s1, 2);
        l0 = l0 * c0 + s0;
        l1 = l1 * c1 + s1;
#pragma unroll
        for (int dj = 0; dj < 8; dj++) {
            oc[dj][0] *= c0; oc[dj][1] *= c0; oc[dj][2] *= c1; oc[dj][3] *= c1;
        }

#pragma unroll
        for (int t = 0; t < 4; t++) {
            uint32_t pa[4];
            pa[0] = pk2(sc[2 * t][0],     sc[2 * t][1]);
            pa[1] = pk2(sc[2 * t][2],     sc[2 * t][3]);
            pa[2] = pk2(sc[2 * t + 1][0], sc[2 * t + 1][1]);
            pa[3] = pk2(sc[2 * t + 1][2], sc[2 * t + 1][3]);
            const int rr = t * 16 + (lane & 7) + ((lane >> 3) & 1) * 8;
#pragma unroll
            for (int dj2 = 0; dj2 < 4; dj2++) {
                const int cc = dj2 * 2 + lh;
                uint32_t vb[4];
                ldm_x4_t(vb, Vb + rr * 128 + ((cc ^ (rr & 7)) * 16));
                mma16816(oc[dj2 * 2],     pa, vb[0], vb[1]);
                mma16816(oc[dj2 * 2 + 1], pa, vb[2], vb[3]);
            }
        }
    }

    // fp8 output, scaled x16 (undone by ascale=1/16 in Wo epilogue)
    const float i0 = 16.f / l0, i1 = 16.f / l1;
    uint8_t* Ob = O + ((size_t)(b * NLQ + qt * 128 + wid * 16 + (lane >> 2))) * NDIM
                    + h * NHD + (lane & 3) * 2;
#pragma unroll
    for (int dj = 0; dj < 8; dj++) {
        *(unsigned short*)(Ob + dj * 8)            = f8x2(oc[dj][0] * i0, oc[dj][1] * i0);
        *(unsigned short*)(Ob + 8 * NDIM + dj * 8) = f8x2(oc[dj][2] * i1, oc[dj][3] * i1);
    }
}

// ---------------------------------------------------------------------------
// Launch
// ---------------------------------------------------------------------------
extern "C" void kernel_launch(void* const* d_in, const int* in_sizes, int n_in,
                              void* d_out, int out_size)
{
    (void)in_sizes; (void)n_in; (void)out_size;
    const float* q_tokens   = (const float*)d_in[0];
    const float* kv_tokens  = (const float*)d_in[1];
    const float* q_ln_w     = (const float*)d_in[2];
    const float* q_ln_b     = (const float*)d_in[3];
    const float* kv_ln_w    = (const float*)d_in[4];
    const float* kv_ln_b    = (const float*)d_in[5];
    const float* mlp_ln_w   = (const float*)d_in[6];
    const float* mlp_ln_b   = (const float*)d_in[7];
    const float* Wq         = (const float*)d_in[8];
    const float* Wk         = (const float*)d_in[9];
    const float* Wv         = (const float*)d_in[10];
    const float* Wo         = (const float*)d_in[11];
    const float* bo         = (const float*)d_in[12];
    const float* fc1_w      = (const float*)d_in[13];
    const float* fc1_b      = (const float*)d_in[14];
    const float* fc2_w      = (const float*)d_in[15];
    const float* fc2_b      = (const float*)d_in[16];
    const float* alpha_attn = (const float*)d_in[17];
    const float* alpha_mlp  = (const float*)d_in[18];
    float* out = (float*)d_out;

    void* p;
    uint8_t *QNB, *KVNB, *CTXB, *HNB, *H1B, *WQB, *WKVB, *WOB, *F1B, *F2B;
    __nv_bfloat16 *QB, *KVB;
    float *RES;
    cudaGetSymbolAddress(&p, g_qnb);  QNB  = (uint8_t*)p;
    cudaGetSymbolAddress(&p, g_kvnb); KVNB = (uint8_t*)p;
    cudaGetSymbolAddress(&p, g_qb);   QB   = (__nv_bfloat16*)p;
    cudaGetSymbolAddress(&p, g_kvb);  KVB  = (__nv_bfloat16*)p;
    cudaGetSymbolAddress(&p, g_ctxb); CTXB = (uint8_t*)p;
    cudaGetSymbolAddress(&p, g_hnb);  HNB  = (uint8_t*)p;
    cudaGetSymbolAddress(&p, g_h1b);  H1B  = (uint8_t*)p;
    cudaGetSymbolAddress(&p, g_wqb);  WQB  = (uint8_t*)p;
    cudaGetSymbolAddress(&p, g_wkvb); WKVB = (uint8_t*)p;
    cudaGetSymbolAddress(&p, g_wob);  WOB  = (uint8_t*)p;
    cudaGetSymbolAddress(&p, g_f1b);  F1B  = (uint8_t*)p;
    cudaGetSymbolAddress(&p, g_f2b);  F2B  = (uint8_t*)p;
    cudaGetSymbolAddress(&p, g_res);  RES  = (float*)p;

    cudaFuncSetAttribute((const void*)gemm_mma<1>, cudaFuncAttributeMaxDynamicSharedMemorySize, GEMM_SMEM);
    cudaFuncSetAttribute((const void*)gemm_mma<2>, cudaFuncAttributeMaxDynamicSharedMemorySize, GEMM_SMEM);
    cudaFuncSetAttribute((const void*)gemm_mma<3>, cudaFuncAttributeMaxDynamicSharedMemorySize, GEMM_SMEM);
    cudaFuncSetAttribute(attn_mma, cudaFuncAttributeMaxDynamicSharedMemorySize, AT_SMEM);

    // Weight fp32 -> fp8 (fused; Wk/Wv concat into WKVB)
    conv6_kernel<<<12288, 256>>>(Wq, Wk, Wv, Wo, fc1_w, fc2_w,
                                 WQB, WKVB, WOB, F1B, F2B);

    // 1) Input LayerNorms (fused q + kv) -> fp8
    ln2_kernel<<<MQ + MKV, 256>>>(q_tokens, q_ln_w, q_ln_b, QNB,
                                  kv_tokens, kv_ln_w, kv_ln_b, KVNB);

    // 2) Projections (fp8 MMA -> bf16 out): Q and fused K|V (N = 2048)
    gemm_mma<3><<<dim3(NDIM/128, MQ/128),  256, GEMM_SMEM>>>(
        QNB, WQB, nullptr, nullptr, nullptr, 1.f, nullptr, QB, nullptr, MQ, NDIM, NDIM);
    gemm_mma<3><<<dim3(KVW/128, MKV/128), 256, GEMM_SMEM>>>(
        KVNB, WKVB, nullptr, nullptr, nullptr, 1.f, nullptr, KVB, nullptr, MKV, KVW, NDIM);

    // 3) Per-head L2 normalization of q and k (bf16 in-place)
    l2norm_bf16_kernel<<<(MQ  * NH) / 8, 256>>>(QB,  NDIM);
    l2norm_bf16_kernel<<<(MKV * NH) / 8, 256>>>(KVB, KVW);

    // 4) Attention (bf16 HMMA) -> fp8 ctx (x16)
    attn_mma<<<dim3(NLQ/128, NH, NB), 256, AT_SMEM>>>(QB, KVB, CTXB);

    // 5) Output projection + attn residual (fp32 out; alpha/16 undoes ctx scale)
    gemm_mma<1><<<dim3(NDIM/128, MQ/128), 256, GEMM_SMEM>>>(
        CTXB, WOB, bo, q_tokens, alpha_attn, 0.0625f, RES, nullptr, nullptr, MQ, NDIM, NDIM);

    // 6) MLP
    ln_f8_kernel<<<MQ, 256>>>(RES, mlp_ln_w, mlp_ln_b, HNB);
    gemm_mma<2><<<dim3(NMH/128, MQ/128), 256, GEMM_SMEM>>>(
        HNB, F1B, fc1_b, nullptr, nullptr, 1.f, nullptr, nullptr, H1B, MQ, NMH, NDIM);
    gemm_mma<1><<<dim3(NDIM/128, MQ/128), 256, GEMM_SMEM>>>(
        H1B, F2B, fc2_b, RES, alpha_mlp, 1.f, out, nullptr, nullptr, MQ, NDIM, NMH);
}